// round 7
// baseline (speedup 1.0000x reference)
#include <cuda_runtime.h>
#include <cuda_fp16.h>
#include <cstdint>

#define H 1024
#define C 56
#define T 64
#define NBLK 148
#define NT 1024

// ---------------- persistent device state (converted weights) ----------------
__device__ __align__(16) __half cWih1td[3 * H * H];   // [gate i/g/o][j][k] : TD half of Wih1
__device__ __align__(16) __half cWih2s [3 * H * H];   // BU half of Wih2
__device__ __align__(16) __half cWih2td[3 * H * H];   // TD half of Wih2
__device__ __align__(16) __half cWih3  [3 * H * H];
__device__ __align__(16) __half cW1[H * H], cW2[H * H], cV2[H * H], cV3[H * H];
__device__ __align__(16) __half cV1[C * H];
__device__ __align__(16) float  cM1 [3 * H * 64];     // fused Wih1_bu @ W0, rows padded to 64
__device__ __align__(16) float  cb1v[3 * H];          // b1 + Wih1_bu @ W0b (reordered)

__device__ __align__(16) float g_s1[H], g_s2[H], g_s3[H], g_BU1[H], g_BU2[H];
__device__ __align__(16) float g_TD1[H], g_TD2[H];
__device__ __align__(16) float g_r1[64], g_r2[H], g_r3[H];

// ---------------- flag-array grid barrier ----------------
// One flag per CTA at 128B stride: arrivals are parallel plain stores to 148
// distinct L2 lines (no single-address atomic serialization, which cost
// ~2.2us/barrier in R1/R6). CTA0 sweeps the flags and publishes g_gen2; all
// CTAs spin on that one word. Generation is monotonic across graph replays;
// comparisons are wrap-safe via signed subtraction.
#define FSTRIDE 32
__device__ volatile unsigned g_flags[NBLK * FSTRIDE];
__device__ volatile unsigned g_gen2;

__device__ __forceinline__ float sigm(float x) { return 1.0f / (1.0f + expf(-x)); }

__device__ __forceinline__ float wred(float v) {
#pragma unroll
    for (int o = 16; o; o >>= 1) v += __shfl_xor_sync(0xffffffffu, v, o);
    return v;
}

// stage CH 16-byte chunks global -> shared with plain loads/stores (warp-cooperative)
template <int CH>
__device__ __forceinline__ void stage_row(void* sdst, const void* gsrc, int lane) {
    uint4* s = (uint4*)sdst;
    const uint4* g = (const uint4*)gsrc;
#pragma unroll
    for (int i = lane; i < CH; i += 32) s[i] = __ldcg(g + i);
}

// lane-partial dot: 1024 fp16 weights (smem) x 1024 fp32 acts (smem).
// 4 iterations x 256 = exactly 1024 elements.
__device__ __forceinline__ float dotp(const __half* __restrict__ ws,
                                      const float* __restrict__ a, int lane) {
    float acc = 0.f;
    int o = lane << 3;
#pragma unroll
    for (int it = 0; it < 4; ++it, o += 256) {
        uint4 u = *reinterpret_cast<const uint4*>(ws + o);
        float4 a0 = *reinterpret_cast<const float4*>(a + o);
        float4 a1 = *reinterpret_cast<const float4*>(a + o + 4);
        float2 f0 = __half22float2(*reinterpret_cast<__half2*>(&u.x));
        float2 f1 = __half22float2(*reinterpret_cast<__half2*>(&u.y));
        float2 f2 = __half22float2(*reinterpret_cast<__half2*>(&u.z));
        float2 f3 = __half22float2(*reinterpret_cast<__half2*>(&u.w));
        acc += f0.x * a0.x + f0.y * a0.y + f1.x * a0.z + f1.y * a0.w
             + f2.x * a1.x + f2.y * a1.y + f3.x * a1.z + f3.y * a1.w;
    }
    return acc;
}

// barrier tail used at the end of every phase:
//   __syncthreads()   (caller already did it)
//   ++ph (all threads), tid0 posts its flag, all warps stage next weights,
//   tid0 (cta0) sweeps flags + publishes, tid0 spins on g_gen2, __syncthreads.
#define BAR_POST()                                            \
    do {                                                      \
        ++ph;                                                 \
        if (tid == 0) { __threadfence(); g_flags[cta * FSTRIDE] = ph; } \
    } while (0)

#define BAR_FINISH()                                          \
    do {                                                      \
        if (tid == 0) {                                       \
            if (cta == 0) {                                   \
                for (;;) {                                    \
                    bool ok = true;                           \
                    _Pragma("unroll 8")                       \
                    for (int i_ = 0; i_ < NBLK; ++i_)         \
                        ok &= ((int)(g_flags[i_ * FSTRIDE] - ph) >= 0); \
                    if (ok) break;                            \
                }                                             \
                __threadfence();                              \
                g_gen2 = ph;                                  \
            }                                                 \
            while ((int)(g_gen2 - ph) < 0) { }                \
            __threadfence();                                  \
        }                                                     \
        __syncthreads();                                      \
    } while (0)

// smem byte offsets
#define OFF_SA   0                      // 21 rows x 2048B (fp16 weight rows)
#define OFF_SB   43008                  // 21 rows x 2048B
#define OFF_SC   86016                  // 7 rows x 2048B
#define OFF_M1   100352                 // 21 rows x 256B (fp32 M1 rows)
#define OFF_ACTA 105728
#define OFF_ACTB 109824
#define OFF_ACTC 113920
#define OFF_N0   118016
#define OFF_GBUF 118272
#define OFF_ZP2  118400
#define SMEM_BYTES 118528
// phase-0 W0 scratch is fp16: H*C*2 = 114,688 B <= SMEM_BYTES.

__global__ void __launch_bounds__(NT, 1) predcells_kernel(
    const float* __restrict__ x,
    const float* __restrict__ W0w, const float* __restrict__ W0b,
    const float* __restrict__ W1w, const float* __restrict__ W1b,
    const float* __restrict__ W2w, const float* __restrict__ W2b,
    const float* __restrict__ Wih1, const float* __restrict__ b1,
    const float* __restrict__ Wih2, const float* __restrict__ b2,
    const float* __restrict__ Wih3, const float* __restrict__ b3,
    const float* __restrict__ V1w, const float* __restrict__ V1b,
    const float* __restrict__ V2w, const float* __restrict__ V2b,
    const float* __restrict__ V3w, const float* __restrict__ V3b,
    const int* __restrict__ iternum, float* __restrict__ out) {
    extern __shared__ char smem[];
    __half* sSA = (__half*)(smem + OFF_SA);
    __half* sSB = (__half*)(smem + OFF_SB);
    __half* sSC = (__half*)(smem + OFF_SC);
    float*  sM1 = (float*)(smem + OFF_M1);
    float*  actA = (float*)(smem + OFF_ACTA);
    float*  actB = (float*)(smem + OFF_ACTB);
    float*  actC = (float*)(smem + OFF_ACTC);
    float*  n0   = (float*)(smem + OFF_N0);
    float*  gbuf = (float*)(smem + OFF_GBUF);
    float*  zp2s = (float*)(smem + OFF_ZP2);

    const int tid = threadIdx.x;
    const int cta = blockIdx.x;
    const int w = tid >> 5;
    const int lane = tid & 31;
    const int nj = (cta < H - 6 * NBLK) ? 7 : 6;
    const int jlw = w / 3, gatew = w % 3;
    const int j1 = cta + jlw * NBLK;                 // row for LSTM-warp roles
    const bool lstmw = (w < 21) && (jlw < nj);
    const int gofs = (gatew == 0) ? 0 : (gatew == 1) ? 2 * H : 3 * H;
    const int jw = cta + w * NBLK;                   // row for w<7 roles
    const int row1 = gatew * H + j1;                 // reordered gate-row index
    const bool v3w = (w >= 21 && w < 28) && ((w - 21) < nj);
    const int jv3 = cta + (w - 21) * NBLK;
    const bool v2w = (w >= 7 && w < 14) && ((w - 7) < nj);
    const int jv2 = cta + (w - 7) * NBLK;

    // every thread takes the same generation snapshot before any barrier
    unsigned ph = g_gen2;

    // =================== phase 0: convert + fuse ===================
    {
        const int gt = cta * NT + tid;
        const int gs = NBLK * NT;
        for (int i = gt; i < 3 * H * H; i += gs) {
            int g = i >> 20;
            int r = i & (H * H - 1);
            int jj = r >> 10, k = r & 1023;
            int orow = ((g == 0) ? 0 : (g == 1) ? 2 * H : 3 * H) + jj;
            const float* w1r = Wih1 + (size_t)orow * (2 * H);
            const float* w2r = Wih2 + (size_t)orow * (2 * H);
            cWih1td[i] = __float2half(w1r[H + k]);
            cWih2s[i]  = __float2half(w2r[k]);
            cWih2td[i] = __float2half(w2r[H + k]);
            cWih3[i]   = __float2half(Wih3[(size_t)orow * H + k]);
        }
        for (int i = gt; i < H * H; i += gs) {
            cW1[i] = __float2half(W1w[i]);
            cW2[i] = __float2half(W2w[i]);
            cV2[i] = __float2half(V2w[i]);
            cV3[i] = __float2half(V3w[i]);
        }
        for (int i = gt; i < C * H; i += gs) cV1[i] = __float2half(V1w[i]);

        // W0 -> smem fp16 scratch (phase 0 only; MUST stay fp16 to fit SMEM_BYTES)
        __half* W0s = (__half*)smem;
        for (int i = tid; i < H * C; i += NT) W0s[i] = __float2half(W0w[i]);
        if (cta == 0) {
            for (int i = tid; i < H; i += NT) {
                g_TD1[i] = 0.f; g_TD2[i] = 0.f;
                g_r2[i] = 0.f; g_r3[i] = 0.f; g_s3[i] = 0.f;
            }
            if (tid < 64) g_r1[tid] = 0.f;
        }
        __syncthreads();

        // M1 = Wih1_bu @ W0 (fp32 accum), cb1 = b1 + Wih1_bu @ W0b
        if (lstmw) {
            const float* wrow = Wih1 + (size_t)(gofs + j1) * (2 * H);
            float acc0 = 0.f, acc1 = 0.f, accb = 0.f;
            for (int k0 = 0; k0 < H; k0 += 32) {
                float wv = wrow[k0 + lane];
                accb += wv * W0b[k0 + lane];
#pragma unroll 8
                for (int kk = 0; kk < 32; ++kk) {
                    float ww = __shfl_sync(0xffffffffu, wv, kk);
                    int k = k0 + kk;
                    acc0 += ww * __half2float(W0s[k * C + lane]);
                    float w1v = (lane < C - 32) ? __half2float(W0s[k * C + lane + 32]) : 0.f;
                    acc1 += ww * w1v;
                }
            }
            cM1[(size_t)row1 * 64 + lane] = acc0;
            if (lane < C - 32) cM1[(size_t)row1 * 64 + lane + 32] = acc1;
            float cb = wred(accb);
            if (lane == 0) cb1v[row1] = b1[gofs + j1] + cb;
        }
    }
    // full grid barrier: all conversions visible before any staging reads them
    __syncthreads();
    BAR_POST();
    BAR_FINISH();

    // hoist loop-invariant biases into registers
    float r_cb1 = 0.f, r_b2 = 0.f, r_b3 = 0.f, r_w1b = 0.f, r_w2b = 0.f;
    float r_v1b = 0.f, r_v2b = 0.f, r_v3b = 0.f;
    if (lstmw) {
        r_cb1 = __ldcg(&cb1v[row1]);
        r_b2  = b2[gofs + j1];
        r_b3  = b3[gofs + j1];
    }
    if (w < 7 && w < nj) { r_w1b = W1b[jw]; r_w2b = W2b[jw]; }
    if (w == 7 && cta < C) r_v1b = V1b[cta];
    if (v2w) r_v2b = V2b[jv2];
    if (v3w) r_v3b = V3b[jv3];

    // stage P1 weights for t=0
    if (lstmw) {
        stage_row<128>(sSA + (size_t)w * 1024, cWih1td + (size_t)row1 * 1024, lane);
        stage_row<128>(sSB + (size_t)w * 1024, cWih2td + (size_t)row1 * 1024, lane);
        stage_row<14>(sM1 + w * 64, cM1 + (size_t)row1 * 64, lane);
    } else if (v3w) {
        stage_row<128>(sSC + (size_t)(w - 21) * 1024, cV3 + (size_t)jv3 * 1024, lane);
    }

    float L0 = 0.f, L1 = 0.f, L2 = 0.f;   // loss partials, live only in cta0/w31

    for (int t = 0; t < T; ++t) {
        // =========== P1: z1 -> s1 ; zp2 ; recon3 = V3 @ s3_prev ; loss0 ===========
        {
            actA[tid] = __ldcg(&g_TD1[tid]);
            actB[tid] = __ldcg(&g_TD2[tid]);
            actC[tid] = __ldcg(&g_s3[tid]);
            if (tid < 64)
                n0[tid] = (tid < C) ? (x[t * C + tid] - __ldcg(&g_r1[tid])) : 0.f;
            __syncthreads();
            if (lstmw) {
                float p = dotp(sSA + (size_t)w * 1024, actA, lane);
                const float* m = sM1 + w * 64;
                p += m[lane] * n0[lane];
                if (lane < C - 32) p += m[lane + 32] * n0[lane + 32];
                float z1 = wred(p);
                float zp = wred(dotp(sSB + (size_t)w * 1024, actB, lane));
                if (lane == 0) { gbuf[w] = z1 + r_cb1; zp2s[w] = zp + r_b2; }
            } else if (v3w) {
                if (t > 0) {
                    float r3 = wred(dotp(sSC + (size_t)(w - 21) * 1024, actC, lane));
                    if (lane == 0) __stcg(&g_r3[jv3], r3 + r_v3b);
                }
            } else if (cta == 0 && w == 31) {
                float v = fabsf(n0[lane]);
                if (lane < C - 32) v += fabsf(n0[lane + 32]);
                L0 += v;
            }
            __syncthreads();
            if (tid < nj) {
                float zi = gbuf[tid * 3], zg = gbuf[tid * 3 + 1], zo = gbuf[tid * 3 + 2];
                __stcg(&g_s1[cta + tid * NBLK], sigm(zo) * tanhf(sigm(zi) * tanhf(zg)));
            }
            __syncthreads();
            BAR_POST();
            if (w < 7 && w < nj)
                stage_row<128>(sSA + (size_t)w * 1024, cW1 + (size_t)jw * 1024, lane);
            else if (w == 7 && cta < C)
                stage_row<128>(sSA + (size_t)7 * 1024, cV1 + (size_t)cta * 1024, lane);
            BAR_FINISH();
        }
        // =========== P2: nTD1 ; BU1 = W1@nTD1 ; recon1 = V1@s1 ; loss1 ===========
        {
            float s1v = __ldcg(&g_s1[tid]);
            float ntd1 = s1v - __ldcg(&g_r2[tid]);
            actA[tid] = ntd1; actB[tid] = s1v;
            if (cta == 0) __stcg(&g_TD1[tid], ntd1);
            __syncthreads();
            if (w < 7 && w < nj) {
                float bu = wred(dotp(sSA + (size_t)w * 1024, actA, lane));
                if (lane == 0) __stcg(&g_BU1[jw], bu + r_w1b);
            } else if (w == 7 && cta < C) {
                float r1 = wred(dotp(sSA + (size_t)7 * 1024, actB, lane));
                if (lane == 0) __stcg(&g_r1[cta], r1 + r_v1b);
            } else if (cta == 0 && w == 31) {
                float v = 0.f;
                for (int m = lane; m < H; m += 32) v += fabsf(actA[m]);
                L1 += v;
            }
            __syncthreads();
            BAR_POST();
            if (lstmw)
                stage_row<128>(sSA + (size_t)w * 1024, cWih2s + (size_t)row1 * 1024, lane);
            BAR_FINISH();
        }
        // =========== P3: z2 = Wih2_s@BU1 + zp2 -> s2 ===========
        {
            actA[tid] = __ldcg(&g_BU1[tid]);
            __syncthreads();
            if (lstmw) {
                float z = wred(dotp(sSA + (size_t)w * 1024, actA, lane));
                if (lane == 0) gbuf[w] = z + zp2s[w];
            }
            __syncthreads();
            if (tid < nj) {
                float zi = gbuf[tid * 3], zg = gbuf[tid * 3 + 1], zo = gbuf[tid * 3 + 2];
                __stcg(&g_s2[cta + tid * NBLK], sigm(zo) * tanhf(sigm(zi) * tanhf(zg)));
            }
            __syncthreads();
            BAR_POST();
            if (w < 7 && w < nj)
                stage_row<128>(sSA + (size_t)w * 1024, cW2 + (size_t)jw * 1024, lane);
            else if (v2w)
                stage_row<128>(sSA + (size_t)w * 1024, cV2 + (size_t)jv2 * 1024, lane);
            BAR_FINISH();
        }
        // =========== P4: nTD2 ; BU2 = W2@nTD2 ; recon2 = V2@s2 ; loss2 ===========
        {
            float s2v = __ldcg(&g_s2[tid]);
            float ntd2 = s2v - __ldcg(&g_r3[tid]);
            actA[tid] = ntd2; actB[tid] = s2v;
            if (cta == 0) __stcg(&g_TD2[tid], ntd2);
            __syncthreads();
            if (w < 7 && w < nj) {
                float bu = wred(dotp(sSA + (size_t)w * 1024, actA, lane));
                if (lane == 0) __stcg(&g_BU2[jw], bu + r_w2b);
            } else if (v2w) {
                float r2 = wred(dotp(sSA + (size_t)w * 1024, actB, lane));
                if (lane == 0) __stcg(&g_r2[jv2], r2 + r_v2b);
            } else if (cta == 0 && w == 31) {
                float v = 0.f;
                for (int m = lane; m < H; m += 32) v += fabsf(actA[m]);
                L2 += v;
            }
            __syncthreads();
            BAR_POST();
            if (lstmw)
                stage_row<128>(sSA + (size_t)w * 1024, cWih3 + (size_t)row1 * 1024, lane);
            BAR_FINISH();
        }
        // =========== P5: z3 = Wih3@BU2 + b3 -> s3 ===========
        {
            actA[tid] = __ldcg(&g_BU2[tid]);
            __syncthreads();
            if (lstmw) {
                float z = wred(dotp(sSA + (size_t)w * 1024, actA, lane));
                if (lane == 0) gbuf[w] = z + r_b3;
            }
            __syncthreads();
            if (tid < nj) {
                float zi = gbuf[tid * 3], zg = gbuf[tid * 3 + 1], zo = gbuf[tid * 3 + 2];
                __stcg(&g_s3[cta + tid * NBLK], sigm(zo) * tanhf(sigm(zi) * tanhf(zg)));
            }
            __syncthreads();
            BAR_POST();
            if (t < T - 1) {   // stage next step's P1
                if (lstmw) {
                    stage_row<128>(sSA + (size_t)w * 1024, cWih1td + (size_t)row1 * 1024, lane);
                    stage_row<128>(sSB + (size_t)w * 1024, cWih2td + (size_t)row1 * 1024, lane);
                    stage_row<14>(sM1 + w * 64, cM1 + (size_t)row1 * 64, lane);
                } else if (v3w) {
                    stage_row<128>(sSC + (size_t)(w - 21) * 1024, cV3 + (size_t)jv3 * 1024, lane);
                }
            }
            BAR_FINISH();
        }
    }

    if (cta == 0 && w == 31) {
        float l0 = wred(L0), l1 = wred(L1), l2 = wred(L2);
        if (lane == 0) {
            float lam = (iternum[0] <= 1000) ? 1e-4f : 1e-2f;
            out[0] = l0 + lam * l1 + lam * lam * l2;
        }
    }
}

extern "C" void kernel_launch(void* const* d_in, const int* in_sizes, int n_in,
                              void* d_out, int out_size) {
    (void)in_sizes; (void)n_in; (void)out_size;
    const float* x    = (const float*)d_in[0];
    const float* W0w  = (const float*)d_in[1];
    const float* W0b  = (const float*)d_in[2];
    const float* W1w  = (const float*)d_in[3];
    const float* W1b  = (const float*)d_in[4];
    const float* W2w  = (const float*)d_in[5];
    const float* W2b  = (const float*)d_in[6];
    const float* Wih1 = (const float*)d_in[7];
    const float* b1   = (const float*)d_in[8];
    const float* Wih2 = (const float*)d_in[9];
    const float* b2   = (const float*)d_in[10];
    const float* Wih3 = (const float*)d_in[11];
    const float* b3   = (const float*)d_in[12];
    const float* V1w  = (const float*)d_in[13];
    const float* V1b  = (const float*)d_in[14];
    const float* V2w  = (const float*)d_in[15];
    const float* V2b  = (const float*)d_in[16];
    const float* V3w  = (const float*)d_in[17];
    const float* V3b  = (const float*)d_in[18];
    const int*   itn  = (const int*)d_in[19];

    static bool attr_set = false;
    if (!attr_set) {
        cudaFuncSetAttribute(predcells_kernel,
                             cudaFuncAttributeMaxDynamicSharedMemorySize, SMEM_BYTES);
        attr_set = true;
    }
    predcells_kernel<<<NBLK, NT, SMEM_BYTES>>>(
        x, W0w, W0b, W1w, W1b, W2w, W2b, Wih1, b1, Wih2, b2, Wih3, b3,
        V1w, V1b, V2w, V2b, V3w, V3b, itn, (float*)d_out);
}

// round 8
// speedup vs baseline: 2.7767x; 2.7767x over previous
#include <cuda_runtime.h>
#include <cuda_fp16.h>
#include <cstdint>

#define H 1024
#define C 56
#define T 64
#define NBLK 148
#define NT 1024

// ---------------- persistent device state (converted weights) ----------------
__device__ __align__(16) __half cWih1td[3 * H * H];   // [gate i/g/o][j][k] : TD half of Wih1
__device__ __align__(16) __half cWih2s [3 * H * H];   // BU half of Wih2
__device__ __align__(16) __half cWih2td[3 * H * H];   // TD half of Wih2
__device__ __align__(16) __half cWih3  [3 * H * H];
__device__ __align__(16) __half cW1[H * H], cW2[H * H], cV2[H * H], cV3[H * H];
__device__ __align__(16) __half cV1[C * H];
__device__ __align__(16) float  cM1 [3 * H * 64];     // fused Wih1_bu @ W0, rows padded to 64
__device__ __align__(16) float  cb1v[3 * H];          // b1 + Wih1_bu @ W0b (reordered)

__device__ __align__(16) float g_s1[H], g_s2[H], g_s3[H], g_BU1[H], g_BU2[H];
__device__ __align__(16) float g_TD1[H], g_TD2[H];
__device__ __align__(16) float g_r1[64], g_r2[H], g_r3[H];

// ---------------- monotonic-counter grid barrier ----------------
// Arrive: tid0 does __threadfence + fire-and-forget atomicAdd (RED, no return;
// 148 same-address REDs serialize in ~126 cyc total). Wait: every CTA's tid0
// polls the counter directly for cnt >= base + n*NBLK — no generation word, no
// reset, no publish round-trip (R6's reset+publish cost ~3.6us/barrier; R7's
// centralized flag sweep cost ~9.5us). Counter is never reset; the per-launch
// base is read from g_base at entry (written only at the END of the previous
// launch, so it is stable during this one). Wrap-safe via signed compares.
__device__ unsigned g_cnt2;    // zero at load; grows monotonically forever
__device__ unsigned g_base;    // counter value at the start of this launch

#define NBAR_TOTAL (1 + 5 * T)  // conv barrier + 5 per step

__device__ __forceinline__ float sigm(float x) { return 1.0f / (1.0f + expf(-x)); }

__device__ __forceinline__ float wred(float v) {
#pragma unroll
    for (int o = 16; o; o >>= 1) v += __shfl_xor_sync(0xffffffffu, v, o);
    return v;
}

// stage CH 16-byte chunks global -> shared with plain loads/stores (warp-cooperative)
template <int CH>
__device__ __forceinline__ void stage_row(void* sdst, const void* gsrc, int lane) {
    uint4* s = (uint4*)sdst;
    const uint4* g = (const uint4*)gsrc;
#pragma unroll
    for (int i = lane; i < CH; i += 32) s[i] = __ldcg(g + i);
}

// lane-partial dot: 1024 fp16 weights (smem) x 1024 fp32 acts (smem).
__device__ __forceinline__ float dotp(const __half* __restrict__ ws,
                                      const float* __restrict__ a, int lane) {
    float acc = 0.f;
    int o = lane << 3;
#pragma unroll
    for (int it = 0; it < 4; ++it, o += 256) {
        uint4 u = *reinterpret_cast<const uint4*>(ws + o);
        float4 a0 = *reinterpret_cast<const float4*>(a + o);
        float4 a1 = *reinterpret_cast<const float4*>(a + o + 4);
        float2 f0 = __half22float2(*reinterpret_cast<__half2*>(&u.x));
        float2 f1 = __half22float2(*reinterpret_cast<__half2*>(&u.y));
        float2 f2 = __half22float2(*reinterpret_cast<__half2*>(&u.z));
        float2 f3 = __half22float2(*reinterpret_cast<__half2*>(&u.w));
        acc += f0.x * a0.x + f0.y * a0.y + f1.x * a0.z + f1.y * a0.w
             + f2.x * a1.x + f2.y * a1.y + f3.x * a1.z + f3.y * a1.w;
    }
    return acc;
}

// arrive: release-fence + RED increment; nbar advances on ALL threads
#define BAR_ARRIVE()                                           \
    do {                                                       \
        ++nbar;                                                \
        if (tid == 0) { __threadfence(); atomicAdd(&g_cnt2, 1u); } \
    } while (0)

// wait: tid0 polls counter for this barrier's absolute target, then acquire
#define BAR_WAIT()                                             \
    do {                                                       \
        if (tid == 0) {                                        \
            unsigned tgt = base + nbar * NBLK;                 \
            while ((int)(*(volatile unsigned*)&g_cnt2 - tgt) < 0) { } \
            __threadfence();                                   \
        }                                                      \
        __syncthreads();                                       \
    } while (0)

// smem byte offsets
#define OFF_SA   0                      // 21 rows x 2048B (fp16 weight rows)
#define OFF_SB   43008                  // 21 rows x 2048B
#define OFF_SC   86016                  // 7 rows x 2048B
#define OFF_M1   100352                 // 21 rows x 256B (fp32 M1 rows)
#define OFF_ACTA 105728
#define OFF_ACTB 109824
#define OFF_ACTC 113920
#define OFF_N0   118016
#define OFF_GBUF 118272
#define OFF_ZP2  118400
#define SMEM_BYTES 118528
// phase-0 W0 scratch is fp16: H*C*2 = 114,688 B <= SMEM_BYTES.

__global__ void __launch_bounds__(NT, 1) predcells_kernel(
    const float* __restrict__ x,
    const float* __restrict__ W0w, const float* __restrict__ W0b,
    const float* __restrict__ W1w, const float* __restrict__ W1b,
    const float* __restrict__ W2w, const float* __restrict__ W2b,
    const float* __restrict__ Wih1, const float* __restrict__ b1,
    const float* __restrict__ Wih2, const float* __restrict__ b2,
    const float* __restrict__ Wih3, const float* __restrict__ b3,
    const float* __restrict__ V1w, const float* __restrict__ V1b,
    const float* __restrict__ V2w, const float* __restrict__ V2b,
    const float* __restrict__ V3w, const float* __restrict__ V3b,
    const int* __restrict__ iternum, float* __restrict__ out) {
    extern __shared__ char smem[];
    __half* sSA = (__half*)(smem + OFF_SA);
    __half* sSB = (__half*)(smem + OFF_SB);
    __half* sSC = (__half*)(smem + OFF_SC);
    float*  sM1 = (float*)(smem + OFF_M1);
    float*  actA = (float*)(smem + OFF_ACTA);
    float*  actB = (float*)(smem + OFF_ACTB);
    float*  actC = (float*)(smem + OFF_ACTC);
    float*  n0   = (float*)(smem + OFF_N0);
    float*  gbuf = (float*)(smem + OFF_GBUF);
    float*  zp2s = (float*)(smem + OFF_ZP2);

    const int tid = threadIdx.x;
    const int cta = blockIdx.x;
    const int w = tid >> 5;
    const int lane = tid & 31;
    const int nj = (cta < H - 6 * NBLK) ? 7 : 6;
    const int jlw = w / 3, gatew = w % 3;
    const int j1 = cta + jlw * NBLK;                 // row for LSTM-warp roles
    const bool lstmw = (w < 21) && (jlw < nj);
    const int gofs = (gatew == 0) ? 0 : (gatew == 1) ? 2 * H : 3 * H;
    const int jw = cta + w * NBLK;                   // row for w<7 roles
    const int row1 = gatew * H + j1;                 // reordered gate-row index
    const bool v3w = (w >= 21 && w < 28) && ((w - 21) < nj);
    const int jv3 = cta + (w - 21) * NBLK;
    const bool v2w = (w >= 7 && w < 14) && ((w - 7) < nj);
    const int jv2 = cta + (w - 7) * NBLK;

    // stable per-launch counter base (written only at the end of prior launch)
    const unsigned base = *(volatile unsigned*)&g_base;
    unsigned nbar = 0;

    // =================== phase 0: convert + fuse ===================
    {
        const int gt = cta * NT + tid;
        const int gs = NBLK * NT;
        for (int i = gt; i < 3 * H * H; i += gs) {
            int g = i >> 20;
            int r = i & (H * H - 1);
            int jj = r >> 10, k = r & 1023;
            int orow = ((g == 0) ? 0 : (g == 1) ? 2 * H : 3 * H) + jj;
            const float* w1r = Wih1 + (size_t)orow * (2 * H);
            const float* w2r = Wih2 + (size_t)orow * (2 * H);
            cWih1td[i] = __float2half(w1r[H + k]);
            cWih2s[i]  = __float2half(w2r[k]);
            cWih2td[i] = __float2half(w2r[H + k]);
            cWih3[i]   = __float2half(Wih3[(size_t)orow * H + k]);
        }
        for (int i = gt; i < H * H; i += gs) {
            cW1[i] = __float2half(W1w[i]);
            cW2[i] = __float2half(W2w[i]);
            cV2[i] = __float2half(V2w[i]);
            cV3[i] = __float2half(V3w[i]);
        }
        for (int i = gt; i < C * H; i += gs) cV1[i] = __float2half(V1w[i]);

        // W0 -> smem fp16 scratch (phase 0 only; MUST stay fp16 to fit SMEM_BYTES)
        __half* W0s = (__half*)smem;
        for (int i = tid; i < H * C; i += NT) W0s[i] = __float2half(W0w[i]);
        if (cta == 0) {
            for (int i = tid; i < H; i += NT) {
                g_TD1[i] = 0.f; g_TD2[i] = 0.f;
                g_r2[i] = 0.f; g_r3[i] = 0.f; g_s3[i] = 0.f;
            }
            if (tid < 64) g_r1[tid] = 0.f;
        }
        __syncthreads();

        // M1 = Wih1_bu @ W0 (fp32 accum), cb1 = b1 + Wih1_bu @ W0b
        if (lstmw) {
            const float* wrow = Wih1 + (size_t)(gofs + j1) * (2 * H);
            float acc0 = 0.f, acc1 = 0.f, accb = 0.f;
            for (int k0 = 0; k0 < H; k0 += 32) {
                float wv = wrow[k0 + lane];
                accb += wv * W0b[k0 + lane];
#pragma unroll 8
                for (int kk = 0; kk < 32; ++kk) {
                    float ww = __shfl_sync(0xffffffffu, wv, kk);
                    int k = k0 + kk;
                    acc0 += ww * __half2float(W0s[k * C + lane]);
                    float w1v = (lane < C - 32) ? __half2float(W0s[k * C + lane + 32]) : 0.f;
                    acc1 += ww * w1v;
                }
            }
            cM1[(size_t)row1 * 64 + lane] = acc0;
            if (lane < C - 32) cM1[(size_t)row1 * 64 + lane + 32] = acc1;
            float cb = wred(accb);
            if (lane == 0) cb1v[row1] = b1[gofs + j1] + cb;
        }
    }
    // full grid barrier: all conversions visible before any staging reads them
    __syncthreads();
    BAR_ARRIVE();
    BAR_WAIT();

    // hoist loop-invariant biases into registers
    float r_cb1 = 0.f, r_b2 = 0.f, r_b3 = 0.f, r_w1b = 0.f, r_w2b = 0.f;
    float r_v1b = 0.f, r_v2b = 0.f, r_v3b = 0.f;
    if (lstmw) {
        r_cb1 = __ldcg(&cb1v[row1]);
        r_b2  = b2[gofs + j1];
        r_b3  = b3[gofs + j1];
    }
    if (w < 7 && w < nj) { r_w1b = W1b[jw]; r_w2b = W2b[jw]; }
    if (w == 7 && cta < C) r_v1b = V1b[cta];
    if (v2w) r_v2b = V2b[jv2];
    if (v3w) r_v3b = V3b[jv3];

    // stage P1 weights for t=0
    if (lstmw) {
        stage_row<128>(sSA + (size_t)w * 1024, cWih1td + (size_t)row1 * 1024, lane);
        stage_row<128>(sSB + (size_t)w * 1024, cWih2td + (size_t)row1 * 1024, lane);
        stage_row<14>(sM1 + w * 64, cM1 + (size_t)row1 * 64, lane);
    } else if (v3w) {
        stage_row<128>(sSC + (size_t)(w - 21) * 1024, cV3 + (size_t)jv3 * 1024, lane);
    }

    float L0 = 0.f, L1 = 0.f, L2 = 0.f;   // loss partials, live only in cta0/w31

    for (int t = 0; t < T; ++t) {
        // =========== P1: z1 -> s1 ; zp2 ; recon3 = V3 @ s3_prev ; loss0 ===========
        {
            actA[tid] = __ldcg(&g_TD1[tid]);
            actB[tid] = __ldcg(&g_TD2[tid]);
            actC[tid] = __ldcg(&g_s3[tid]);
            if (tid < 64)
                n0[tid] = (tid < C) ? (x[t * C + tid] - __ldcg(&g_r1[tid])) : 0.f;
            __syncthreads();
            if (lstmw) {
                float p = dotp(sSA + (size_t)w * 1024, actA, lane);
                const float* m = sM1 + w * 64;
                p += m[lane] * n0[lane];
                if (lane < C - 32) p += m[lane + 32] * n0[lane + 32];
                float z1 = wred(p);
                float zp = wred(dotp(sSB + (size_t)w * 1024, actB, lane));
                if (lane == 0) { gbuf[w] = z1 + r_cb1; zp2s[w] = zp + r_b2; }
            } else if (v3w) {
                if (t > 0) {
                    float r3 = wred(dotp(sSC + (size_t)(w - 21) * 1024, actC, lane));
                    if (lane == 0) __stcg(&g_r3[jv3], r3 + r_v3b);
                }
            } else if (cta == 0 && w == 31) {
                float v = fabsf(n0[lane]);
                if (lane < C - 32) v += fabsf(n0[lane + 32]);
                L0 += v;
            }
            __syncthreads();
            if (tid < nj) {
                float zi = gbuf[tid * 3], zg = gbuf[tid * 3 + 1], zo = gbuf[tid * 3 + 2];
                __stcg(&g_s1[cta + tid * NBLK], sigm(zo) * tanhf(sigm(zi) * tanhf(zg)));
            }
            __syncthreads();
            BAR_ARRIVE();
            if (w < 7 && w < nj)
                stage_row<128>(sSA + (size_t)w * 1024, cW1 + (size_t)jw * 1024, lane);
            else if (w == 7 && cta < C)
                stage_row<128>(sSA + (size_t)7 * 1024, cV1 + (size_t)cta * 1024, lane);
            BAR_WAIT();
        }
        // =========== P2: nTD1 ; BU1 = W1@nTD1 ; recon1 = V1@s1 ; loss1 ===========
        {
            float s1v = __ldcg(&g_s1[tid]);
            float ntd1 = s1v - __ldcg(&g_r2[tid]);
            actA[tid] = ntd1; actB[tid] = s1v;
            if (cta == 0) __stcg(&g_TD1[tid], ntd1);
            __syncthreads();
            if (w < 7 && w < nj) {
                float bu = wred(dotp(sSA + (size_t)w * 1024, actA, lane));
                if (lane == 0) __stcg(&g_BU1[jw], bu + r_w1b);
            } else if (w == 7 && cta < C) {
                float r1 = wred(dotp(sSA + (size_t)7 * 1024, actB, lane));
                if (lane == 0) __stcg(&g_r1[cta], r1 + r_v1b);
            } else if (cta == 0 && w == 31) {
                float v = 0.f;
                for (int m = lane; m < H; m += 32) v += fabsf(actA[m]);
                L1 += v;
            }
            __syncthreads();
            BAR_ARRIVE();
            if (lstmw)
                stage_row<128>(sSA + (size_t)w * 1024, cWih2s + (size_t)row1 * 1024, lane);
            BAR_WAIT();
        }
        // =========== P3: z2 = Wih2_s@BU1 + zp2 -> s2 ===========
        {
            actA[tid] = __ldcg(&g_BU1[tid]);
            __syncthreads();
            if (lstmw) {
                float z = wred(dotp(sSA + (size_t)w * 1024, actA, lane));
                if (lane == 0) gbuf[w] = z + zp2s[w];
            }
            __syncthreads();
            if (tid < nj) {
                float zi = gbuf[tid * 3], zg = gbuf[tid * 3 + 1], zo = gbuf[tid * 3 + 2];
                __stcg(&g_s2[cta + tid * NBLK], sigm(zo) * tanhf(sigm(zi) * tanhf(zg)));
            }
            __syncthreads();
            BAR_ARRIVE();
            if (w < 7 && w < nj)
                stage_row<128>(sSA + (size_t)w * 1024, cW2 + (size_t)jw * 1024, lane);
            else if (v2w)
                stage_row<128>(sSA + (size_t)w * 1024, cV2 + (size_t)jv2 * 1024, lane);
            BAR_WAIT();
        }
        // =========== P4: nTD2 ; BU2 = W2@nTD2 ; recon2 = V2@s2 ; loss2 ===========
        {
            float s2v = __ldcg(&g_s2[tid]);
            float ntd2 = s2v - __ldcg(&g_r3[tid]);
            actA[tid] = ntd2; actB[tid] = s2v;
            if (cta == 0) __stcg(&g_TD2[tid], ntd2);
            __syncthreads();
            if (w < 7 && w < nj) {
                float bu = wred(dotp(sSA + (size_t)w * 1024, actA, lane));
                if (lane == 0) __stcg(&g_BU2[jw], bu + r_w2b);
            } else if (v2w) {
                float r2 = wred(dotp(sSA + (size_t)w * 1024, actB, lane));
                if (lane == 0) __stcg(&g_r2[jv2], r2 + r_v2b);
            } else if (cta == 0 && w == 31) {
                float v = 0.f;
                for (int m = lane; m < H; m += 32) v += fabsf(actA[m]);
                L2 += v;
            }
            __syncthreads();
            BAR_ARRIVE();
            if (lstmw)
                stage_row<128>(sSA + (size_t)w * 1024, cWih3 + (size_t)row1 * 1024, lane);
            BAR_WAIT();
        }
        // =========== P5: z3 = Wih3@BU2 + b3 -> s3 ===========
        {
            actA[tid] = __ldcg(&g_BU2[tid]);
            __syncthreads();
            if (lstmw) {
                float z = wred(dotp(sSA + (size_t)w * 1024, actA, lane));
                if (lane == 0) gbuf[w] = z + r_b3;
            }
            __syncthreads();
            if (tid < nj) {
                float zi = gbuf[tid * 3], zg = gbuf[tid * 3 + 1], zo = gbuf[tid * 3 + 2];
                __stcg(&g_s3[cta + tid * NBLK], sigm(zo) * tanhf(sigm(zi) * tanhf(zg)));
            }
            __syncthreads();
            BAR_ARRIVE();
            if (t < T - 1) {   // stage next step's P1
                if (lstmw) {
                    stage_row<128>(sSA + (size_t)w * 1024, cWih1td + (size_t)row1 * 1024, lane);
                    stage_row<128>(sSB + (size_t)w * 1024, cWih2td + (size_t)row1 * 1024, lane);
                    stage_row<14>(sM1 + w * 64, cM1 + (size_t)row1 * 64, lane);
                } else if (v3w) {
                    stage_row<128>(sSC + (size_t)(w - 21) * 1024, cV3 + (size_t)jv3 * 1024, lane);
                }
            }
            BAR_WAIT();
        }
    }

    // cta0 publishes the next launch's counter base; safe because after ITS
    // final poll the counter has reached its final value (all arrivals done).
    if (cta == 0 && tid == 0)
        *(volatile unsigned*)&g_base = base + (unsigned)NBAR_TOTAL * NBLK;

    if (cta == 0 && w == 31) {
        float l0 = wred(L0), l1 = wred(L1), l2 = wred(L2);
        if (lane == 0) {
            float lam = (iternum[0] <= 1000) ? 1e-4f : 1e-2f;
            out[0] = l0 + lam * l1 + lam * lam * l2;
        }
    }
}

extern "C" void kernel_launch(void* const* d_in, const int* in_sizes, int n_in,
                              void* d_out, int out_size) {
    (void)in_sizes; (void)n_in; (void)out_size;
    const float* x    = (const float*)d_in[0];
    const float* W0w  = (const float*)d_in[1];
    const float* W0b  = (const float*)d_in[2];
    const float* W1w  = (const float*)d_in[3];
    const float* W1b  = (const float*)d_in[4];
    const float* W2w  = (const float*)d_in[5];
    const float* W2b  = (const float*)d_in[6];
    const float* Wih1 = (const float*)d_in[7];
    const float* b1   = (const float*)d_in[8];
    const float* Wih2 = (const float*)d_in[9];
    const float* b2   = (const float*)d_in[10];
    const float* Wih3 = (const float*)d_in[11];
    const float* b3   = (const float*)d_in[12];
    const float* V1w  = (const float*)d_in[13];
    const float* V1b  = (const float*)d_in[14];
    const float* V2w  = (const float*)d_in[15];
    const float* V2b  = (const float*)d_in[16];
    const float* V3w  = (const float*)d_in[17];
    const float* V3b  = (const float*)d_in[18];
    const int*   itn  = (const int*)d_in[19];

    static bool attr_set = false;
    if (!attr_set) {
        cudaFuncSetAttribute(predcells_kernel,
                             cudaFuncAttributeMaxDynamicSharedMemorySize, SMEM_BYTES);
        attr_set = true;
    }
    predcells_kernel<<<NBLK, NT, SMEM_BYTES>>>(
        x, W0w, W0b, W1w, W1b, W2w, W2b, Wih1, b1, Wih2, b2, Wih3, b3,
        V1w, V1b, V2w, V2b, V3w, V3b, itn, (float*)d_out);
}

// round 9
// speedup vs baseline: 3.5341x; 1.2728x over previous
#include <cuda_runtime.h>
#include <cuda_fp16.h>
#include <cstdint>

#define H 1024
#define C 56
#define T 64
#define NBLK 148
#define NT 1024

// ---------------- persistent device state (converted weights) ----------------
__device__ __align__(16) __half cWih1td[3 * H * H];   // [gate i/g/o][j][k] : TD half of Wih1
__device__ __align__(16) __half cWih2s [3 * H * H];   // BU half of Wih2
__device__ __align__(16) __half cWih2td[3 * H * H];   // TD half of Wih2
__device__ __align__(16) __half cWih3  [3 * H * H];
__device__ __align__(16) __half cW1[H * H], cW2[H * H], cV2[H * H], cV3[H * H];
__device__ __align__(16) __half cV1[C * H];
__device__ __align__(16) float  cM1 [3 * H * 64];     // fused Wih1_bu @ W0, rows padded to 64
__device__ __align__(16) float  cb1v[3 * H];          // b1 + Wih1_bu @ W0b (reordered)

__device__ __align__(16) float g_s1[H], g_s2[H], g_s3[H], g_BU1[H], g_BU2[H];
__device__ __align__(16) float g_TD1[H], g_TD2[H];
__device__ __align__(16) float g_r1[64], g_r2[H], g_r3[H];

// ---------------- monotonic-counter grid barrier (R8-proven) ----------------
__device__ unsigned g_cnt2;    // zero at load; grows monotonically forever
__device__ unsigned g_base;    // counter value at the start of this launch

#define NBAR_TOTAL (1 + 3 * T)  // conv barrier + 3 per step (pipelined)

__device__ __forceinline__ float sigm(float x) { return 1.0f / (1.0f + expf(-x)); }

__device__ __forceinline__ float wred(float v) {
#pragma unroll
    for (int o = 16; o; o >>= 1) v += __shfl_xor_sync(0xffffffffu, v, o);
    return v;
}

template <int CH>
__device__ __forceinline__ void stage_row(void* sdst, const void* gsrc, int lane) {
    uint4* s = (uint4*)sdst;
    const uint4* g = (const uint4*)gsrc;
#pragma unroll
    for (int i = lane; i < CH; i += 32) s[i] = __ldcg(g + i);
}

// lane-partial dot: 1024 fp16 weights (smem) x 1024 fp32 acts (smem)
__device__ __forceinline__ float dotp(const __half* __restrict__ ws,
                                      const float* __restrict__ a, int lane) {
    float acc = 0.f;
    int o = lane << 3;
#pragma unroll
    for (int it = 0; it < 4; ++it, o += 256) {
        uint4 u = *reinterpret_cast<const uint4*>(ws + o);
        float4 a0 = *reinterpret_cast<const float4*>(a + o);
        float4 a1 = *reinterpret_cast<const float4*>(a + o + 4);
        float2 f0 = __half22float2(*reinterpret_cast<__half2*>(&u.x));
        float2 f1 = __half22float2(*reinterpret_cast<__half2*>(&u.y));
        float2 f2 = __half22float2(*reinterpret_cast<__half2*>(&u.z));
        float2 f3 = __half22float2(*reinterpret_cast<__half2*>(&u.w));
        acc += f0.x * a0.x + f0.y * a0.y + f1.x * a0.z + f1.y * a0.w
             + f2.x * a1.x + f2.y * a1.y + f3.x * a1.z + f3.y * a1.w;
    }
    return acc;
}

#define BAR_ARRIVE()                                           \
    do {                                                       \
        ++nbar;                                                \
        if (tid == 0) { __threadfence(); atomicAdd(&g_cnt2, 1u); } \
    } while (0)

#define BAR_WAIT()                                             \
    do {                                                       \
        if (tid == 0) {                                        \
            unsigned tgt = base + nbar * NBLK;                 \
            while ((int)(*(volatile unsigned*)&g_cnt2 - tgt) < 0) { } \
            __threadfence();                                   \
        }                                                      \
        __syncthreads();                                       \
    } while (0)

// ---------------- smem byte offsets ----------------
// SetA (SP0): Wih1td 21 rows | W2 7 | V2 7.  SetB (SP1): Wih2td 21 | Wih3 21 |
// W1 7 | V1 1.  SetC (SP2, ALIASES SetB — disjoint live ranges): Wih2s 21 | V3 7.
#define OFF_A1   0
#define OFF_A2   43008
#define OFF_A3   57344
#define OFF_B1   71680
#define OFF_B2   114688
#define OFF_B3   157696
#define OFF_B4   172032
#define OFF_C1   71680
#define OFF_C2   114688
#define OFF_M1   174080
#define OFF_ACTA 179456
#define OFF_ACTB 183552
#define OFF_ACTC 187648
#define OFF_ACTD 191744
#define OFF_N0   195840
#define OFF_GBUF 196096
#define OFF_ZP2  196224
#define SMEM_BYTES 196352
// phase-0 W0 scratch is fp16: H*C*2 = 114,688 B <= SMEM_BYTES.

__global__ void __launch_bounds__(NT, 1) predcells_kernel(
    const float* __restrict__ x,
    const float* __restrict__ W0w, const float* __restrict__ W0b,
    const float* __restrict__ W1w, const float* __restrict__ W1b,
    const float* __restrict__ W2w, const float* __restrict__ W2b,
    const float* __restrict__ Wih1, const float* __restrict__ b1,
    const float* __restrict__ Wih2, const float* __restrict__ b2,
    const float* __restrict__ Wih3, const float* __restrict__ b3,
    const float* __restrict__ V1w, const float* __restrict__ V1b,
    const float* __restrict__ V2w, const float* __restrict__ V2b,
    const float* __restrict__ V3w, const float* __restrict__ V3b,
    const int* __restrict__ iternum, float* __restrict__ out) {
    extern __shared__ char smem[];
    __half* sA1 = (__half*)(smem + OFF_A1);
    __half* sA2 = (__half*)(smem + OFF_A2);
    __half* sA3 = (__half*)(smem + OFF_A3);
    __half* sB1 = (__half*)(smem + OFF_B1);
    __half* sB2 = (__half*)(smem + OFF_B2);
    __half* sB3 = (__half*)(smem + OFF_B3);
    __half* sB4 = (__half*)(smem + OFF_B4);
    __half* sC1 = (__half*)(smem + OFF_C1);
    __half* sC2 = (__half*)(smem + OFF_C2);
    float*  sM1  = (float*)(smem + OFF_M1);
    float*  actA = (float*)(smem + OFF_ACTA);
    float*  actB = (float*)(smem + OFF_ACTB);
    float*  actC = (float*)(smem + OFF_ACTC);
    float*  actD = (float*)(smem + OFF_ACTD);
    float*  n0   = (float*)(smem + OFF_N0);
    float*  gbuf = (float*)(smem + OFF_GBUF);
    float*  zp2s = (float*)(smem + OFF_ZP2);

    const int tid = threadIdx.x;
    const int cta = blockIdx.x;
    const int w = tid >> 5;
    const int lane = tid & 31;
    const int nj = (cta < H - 6 * NBLK) ? 7 : 6;

    // compute roles
    const int jlw = w / 3, gatew = w % 3;
    const int j1 = cta + jlw * NBLK;
    const bool lstmw = (w < 21) && (jlw < nj);
    const int gofs = (gatew == 0) ? 0 : (gatew == 1) ? 2 * H : 3 * H;
    const int row1 = gatew * H + j1;
    const int jl = w - 21;
    const int j7 = cta + jl * NBLK;
    const bool sevw = (w >= 21 && w < 28) && (jl < nj);
    const bool v1w = (w == 28) && (cta < C);
    const bool lossw = (cta == 0) && (w == 31);

    // staging roles (shifted by 1 so warp 0 / tid0 never stages -> clean poll)
    const int s21 = w - 1;
    const int ssg = s21 % 3, ssjl = s21 / 3;
    const int srow = ssg * H + cta + ssjl * NBLK;
    const bool stg21 = (w >= 1 && w < 22) && (ssjl < nj);
    const int jl7 = w - 22;
    const int sj7 = cta + jl7 * NBLK;
    const bool stg7 = (w >= 22 && w < 29) && (jl7 < nj);
    const bool stgV1 = (w == 29) && (cta < C);

    const unsigned base = *(volatile unsigned*)&g_base;
    unsigned nbar = 0;

    // =================== phase 0: convert + fuse ===================
    {
        const int gt = cta * NT + tid;
        const int gs = NBLK * NT;
        for (int i = gt; i < 3 * H * H; i += gs) {
            int g = i >> 20;
            int r = i & (H * H - 1);
            int jj = r >> 10, k = r & 1023;
            int orow = ((g == 0) ? 0 : (g == 1) ? 2 * H : 3 * H) + jj;
            const float* w1r = Wih1 + (size_t)orow * (2 * H);
            const float* w2r = Wih2 + (size_t)orow * (2 * H);
            cWih1td[i] = __float2half(w1r[H + k]);
            cWih2s[i]  = __float2half(w2r[k]);
            cWih2td[i] = __float2half(w2r[H + k]);
            cWih3[i]   = __float2half(Wih3[(size_t)orow * H + k]);
        }
        for (int i = gt; i < H * H; i += gs) {
            cW1[i] = __float2half(W1w[i]);
            cW2[i] = __float2half(W2w[i]);
            cV2[i] = __float2half(V2w[i]);
            cV3[i] = __float2half(V3w[i]);
        }
        for (int i = gt; i < C * H; i += gs) cV1[i] = __float2half(V1w[i]);

        __half* W0s = (__half*)smem;   // fp16 scratch, fits
        for (int i = tid; i < H * C; i += NT) W0s[i] = __float2half(W0w[i]);
        if (cta == 0) {
            for (int i = tid; i < H; i += NT) {
                g_TD1[i] = 0.f; g_TD2[i] = 0.f;
                g_r2[i] = 0.f; g_r3[i] = 0.f;
                g_s2[i] = 0.f; g_s3[i] = 0.f; g_BU2[i] = 0.f;
            }
            if (tid < 64) g_r1[tid] = 0.f;
        }
        __syncthreads();

        if (lstmw) {
            const float* wrow = Wih1 + (size_t)(gofs + j1) * (2 * H);
            float acc0 = 0.f, acc1 = 0.f, accb = 0.f;
            for (int k0 = 0; k0 < H; k0 += 32) {
                float wv = wrow[k0 + lane];
                accb += wv * W0b[k0 + lane];
#pragma unroll 8
                for (int kk = 0; kk < 32; ++kk) {
                    float ww = __shfl_sync(0xffffffffu, wv, kk);
                    int k = k0 + kk;
                    acc0 += ww * __half2float(W0s[k * C + lane]);
                    float w1v = (lane < C - 32) ? __half2float(W0s[k * C + lane + 32]) : 0.f;
                    acc1 += ww * w1v;
                }
            }
            cM1[(size_t)row1 * 64 + lane] = acc0;
            if (lane < C - 32) cM1[(size_t)row1 * 64 + lane + 32] = acc1;
            float cb = wred(accb);
            if (lane == 0) cb1v[row1] = b1[gofs + j1] + cb;
        }
    }
    __syncthreads();
    BAR_ARRIVE();
    BAR_WAIT();

    // hoisted biases
    float r_cb1 = 0.f, r_b2 = 0.f, r_b3 = 0.f;
    float r_w1b = 0.f, r_w2b = 0.f, r_v2b = 0.f, r_v3b = 0.f, r_v1b = 0.f;
    if (lstmw) {
        r_cb1 = __ldcg(&cb1v[row1]);
        r_b2  = b2[gofs + j1];
        r_b3  = b3[gofs + j1];
    }
    if (sevw) { r_w1b = W1b[j7]; r_w2b = W2b[j7]; r_v2b = V2b[j7]; r_v3b = V3b[j7]; }
    if (v1w) r_v1b = V1b[cta];

    // stage SetA + M1 for SP0(0) (after the barrier: conversions now visible)
    if (stg21) {
        stage_row<128>(sA1 + (size_t)s21 * 1024, cWih1td + (size_t)srow * 1024, lane);
        stage_row<14>(sM1 + s21 * 64, cM1 + (size_t)srow * 64, lane);
    } else if (stg7) {
        stage_row<128>(sA2 + (size_t)jl7 * 1024, cW2 + (size_t)sj7 * 1024, lane);
        stage_row<128>(sA3 + (size_t)jl7 * 1024, cV2 + (size_t)sj7 * 1024, lane);
    }

    float L0 = 0.f, L1 = 0.f, L2 = 0.f;

    for (int k = 0; k < T; ++k) {
        // ===== SP0: P1(k) z1->s1  ||  P4(k-1): nTD2, BU2=W2@nTD2, r2=V2@s2, loss2 =====
        {
            float aTD1 = __ldcg(&g_TD1[tid]);
            float s2v  = __ldcg(&g_s2[tid]);
            float r3v  = __ldcg(&g_r3[tid]);
            float ntd2 = s2v - r3v;
            actA[tid] = aTD1; actB[tid] = ntd2; actC[tid] = s2v;
            if (tid < 64)
                n0[tid] = (tid < C) ? (x[k * C + tid] - __ldcg(&g_r1[tid])) : 0.f;
            if (cta == 0) __stcg(&g_TD2[tid], ntd2);
            __syncthreads();
            if (lstmw) {
                float p = dotp(sA1 + (size_t)w * 1024, actA, lane);
                const float* m = sM1 + w * 64;
                p += m[lane] * n0[lane];
                if (lane < C - 32) p += m[lane + 32] * n0[lane + 32];
                float z1 = wred(p);
                if (lane == 0) gbuf[w] = z1 + r_cb1;
            } else if (sevw && k > 0) {
                float bu  = wred(dotp(sA2 + (size_t)jl * 1024, actB, lane));
                float r2n = wred(dotp(sA3 + (size_t)jl * 1024, actC, lane));
                if (lane == 0) {
                    __stcg(&g_BU2[j7], bu + r_w2b);
                    __stcg(&g_r2[j7], r2n + r_v2b);
                }
            } else if (lossw) {
                float v = fabsf(n0[lane]);
                if (lane < C - 32) v += fabsf(n0[lane + 32]);
                L0 += v;
                if (k > 0) {
                    float v2 = 0.f;
                    for (int m2 = lane; m2 < H; m2 += 32) v2 += fabsf(actB[m2]);
                    L2 += v2;
                }
            }
            __syncthreads();
            if (tid < nj) {
                float zi = gbuf[tid * 3], zg = gbuf[tid * 3 + 1], zo = gbuf[tid * 3 + 2];
                __stcg(&g_s1[cta + tid * NBLK], sigm(zo) * tanhf(sigm(zi) * tanhf(zg)));
            }
            __syncthreads();
            BAR_ARRIVE();
            if (stg21) {
                stage_row<128>(sB1 + (size_t)s21 * 1024, cWih2td + (size_t)srow * 1024, lane);
                stage_row<128>(sB2 + (size_t)s21 * 1024, cWih3 + (size_t)srow * 1024, lane);
            } else if (stg7) {
                stage_row<128>(sB3 + (size_t)jl7 * 1024, cW1 + (size_t)sj7 * 1024, lane);
            } else if (stgV1) {
                stage_row<128>(sB4, cV1 + (size_t)cta * 1024, lane);
            }
            BAR_WAIT();
        }
        // ===== SP1: P2(k): zp2, BU1, r1=V1@s1, loss1  ||  P5(k-1): z3->s3 =====
        {
            float aTD2 = __ldcg(&g_TD2[tid]);
            float bu2v = __ldcg(&g_BU2[tid]);
            float s1v  = __ldcg(&g_s1[tid]);
            float r2v  = __ldcg(&g_r2[tid]);
            float ntd1 = s1v - r2v;
            actA[tid] = aTD2; actB[tid] = bu2v; actC[tid] = ntd1; actD[tid] = s1v;
            if (cta == 0) __stcg(&g_TD1[tid], ntd1);
            __syncthreads();
            if (lstmw) {
                float zp = wred(dotp(sB1 + (size_t)w * 1024, actA, lane));
                if (lane == 0) zp2s[w] = zp + r_b2;
                if (k > 0) {
                    float z3 = wred(dotp(sB2 + (size_t)w * 1024, actB, lane));
                    if (lane == 0) gbuf[w] = z3 + r_b3;
                }
            } else if (sevw) {
                float bu = wred(dotp(sB3 + (size_t)jl * 1024, actC, lane));
                if (lane == 0) __stcg(&g_BU1[j7], bu + r_w1b);
            } else if (v1w) {
                float r1n = wred(dotp(sB4, actD, lane));
                if (lane == 0) __stcg(&g_r1[cta], r1n + r_v1b);
            } else if (lossw) {
                float v = 0.f;
                for (int m2 = lane; m2 < H; m2 += 32) v += fabsf(actC[m2]);
                L1 += v;
            }
            __syncthreads();
            if (k > 0 && tid < nj) {
                float zi = gbuf[tid * 3], zg = gbuf[tid * 3 + 1], zo = gbuf[tid * 3 + 2];
                __stcg(&g_s3[cta + tid * NBLK], sigm(zo) * tanhf(sigm(zi) * tanhf(zg)));
            }
            __syncthreads();
            BAR_ARRIVE();
            if (stg21)
                stage_row<128>(sC1 + (size_t)s21 * 1024, cWih2s + (size_t)srow * 1024, lane);
            else if (stg7)
                stage_row<128>(sC2 + (size_t)jl7 * 1024, cV3 + (size_t)sj7 * 1024, lane);
            BAR_WAIT();
        }
        // ===== SP2: P3(k): z2 = Wih2s@BU1 + zp2 -> s2  ||  r3 = V3@s3(k-1) =====
        {
            actA[tid] = __ldcg(&g_BU1[tid]);
            actB[tid] = __ldcg(&g_s3[tid]);
            __syncthreads();
            if (lstmw) {
                float z2 = wred(dotp(sC1 + (size_t)w * 1024, actA, lane));
                if (lane == 0) gbuf[w] = z2 + zp2s[w];
            } else if (sevw && k > 0) {
                float r3n = wred(dotp(sC2 + (size_t)jl * 1024, actB, lane));
                if (lane == 0) __stcg(&g_r3[j7], r3n + r_v3b);
            }
            __syncthreads();
            if (tid < nj) {
                float zi = gbuf[tid * 3], zg = gbuf[tid * 3 + 1], zo = gbuf[tid * 3 + 2];
                __stcg(&g_s2[cta + tid * NBLK], sigm(zo) * tanhf(sigm(zi) * tanhf(zg)));
            }
            __syncthreads();
            BAR_ARRIVE();
            if (k < T - 1) {
                if (stg21) {
                    stage_row<128>(sA1 + (size_t)s21 * 1024, cWih1td + (size_t)srow * 1024, lane);
                } else if (stg7) {
                    stage_row<128>(sA2 + (size_t)jl7 * 1024, cW2 + (size_t)sj7 * 1024, lane);
                    stage_row<128>(sA3 + (size_t)jl7 * 1024, cV2 + (size_t)sj7 * 1024, lane);
                }
            }
            BAR_WAIT();
        }
    }

    // pipeline drain: final loss2 term |nTD2(T-1)| = |s2(T-1) - V3@s3(T-2)|
    // (both written before the last barrier -> visible; no extra barrier needed)
    if (lossw) {
        float v = 0.f;
        for (int m2 = lane; m2 < H; m2 += 32)
            v += fabsf(__ldcg(&g_s2[m2]) - __ldcg(&g_r3[m2]));
        L2 += v;
        float l0 = wred(L0), l1 = wred(L1), l2 = wred(L2);
        if (lane == 0) {
            float lam = (iternum[0] <= 1000) ? 1e-4f : 1e-2f;
            out[0] = l0 + lam * l1 + lam * lam * l2;
        }
    }

    if (cta == 0 && tid == 0)
        *(volatile unsigned*)&g_base = base + (unsigned)NBAR_TOTAL * NBLK;
}

extern "C" void kernel_launch(void* const* d_in, const int* in_sizes, int n_in,
                              void* d_out, int out_size) {
    (void)in_sizes; (void)n_in; (void)out_size;
    const float* x    = (const float*)d_in[0];
    const float* W0w  = (const float*)d_in[1];
    const float* W0b  = (const float*)d_in[2];
    const float* W1w  = (const float*)d_in[3];
    const float* W1b  = (const float*)d_in[4];
    const float* W2w  = (const float*)d_in[5];
    const float* W2b  = (const float*)d_in[6];
    const float* Wih1 = (const float*)d_in[7];
    const float* b1   = (const float*)d_in[8];
    const float* Wih2 = (const float*)d_in[9];
    const float* b2   = (const float*)d_in[10];
    const float* Wih3 = (const float*)d_in[11];
    const float* b3   = (const float*)d_in[12];
    const float* V1w  = (const float*)d_in[13];
    const float* V1b  = (const float*)d_in[14];
    const float* V2w  = (const float*)d_in[15];
    const float* V2b  = (const float*)d_in[16];
    const float* V3w  = (const float*)d_in[17];
    const float* V3b  = (const float*)d_in[18];
    const int*   itn  = (const int*)d_in[19];

    static bool attr_set = false;
    if (!attr_set) {
        cudaFuncSetAttribute(predcells_kernel,
                             cudaFuncAttributeMaxDynamicSharedMemorySize, SMEM_BYTES);
        attr_set = true;
    }
    predcells_kernel<<<NBLK, NT, SMEM_BYTES>>>(
        x, W0w, W0b, W1w, W1b, W2w, W2b, Wih1, b1, Wih2, b2, Wih3, b3,
        V1w, V1b, V2w, V2b, V3w, V3b, itn, (float*)d_out);
}

// round 10
// speedup vs baseline: 3.7388x; 1.0579x over previous
#include <cuda_runtime.h>
#include <cuda_fp16.h>
#include <cstdint>

#define H 1024
#define C 56
#define T 64
#define NBLK 148
#define NT 1024

// ---------------- persistent global state (activations only; weights live in smem) ----
__device__ __align__(16) float g_s1[H], g_s2[H], g_s3[H], g_BU1[H], g_BU2[H];
__device__ __align__(16) float g_TD1[H], g_TD2[H];
__device__ __align__(16) float g_r1[64], g_r2[H], g_r3[H];

// ---------------- monotonic-counter grid barrier (R8/R9-proven) ----------------
__device__ unsigned g_cnt2;    // zero at load; grows monotonically forever
__device__ unsigned g_base;    // counter value at the start of this launch

#define NBAR_TOTAL (1 + 3 * T)

__device__ __forceinline__ float sigm(float x) { return 1.0f / (1.0f + expf(-x)); }

__device__ __forceinline__ float wred(float v) {
#pragma unroll
    for (int o = 16; o; o >>= 1) v += __shfl_xor_sync(0xffffffffu, v, o);
    return v;
}

// lane-partial dot: 1024 fp16 weights (smem) x 1024 fp32 acts (smem)
__device__ __forceinline__ float dotp(const __half* __restrict__ ws,
                                      const float* __restrict__ a, int lane) {
    float acc = 0.f;
    int o = lane << 3;
#pragma unroll
    for (int it = 0; it < 4; ++it, o += 256) {
        uint4 u = *reinterpret_cast<const uint4*>(ws + o);
        float4 a0 = *reinterpret_cast<const float4*>(a + o);
        float4 a1 = *reinterpret_cast<const float4*>(a + o + 4);
        float2 f0 = __half22float2(*reinterpret_cast<__half2*>(&u.x));
        float2 f1 = __half22float2(*reinterpret_cast<__half2*>(&u.y));
        float2 f2 = __half22float2(*reinterpret_cast<__half2*>(&u.z));
        float2 f3 = __half22float2(*reinterpret_cast<__half2*>(&u.w));
        acc += f0.x * a0.x + f0.y * a0.y + f1.x * a0.z + f1.y * a0.w
             + f2.x * a1.x + f2.y * a1.y + f3.x * a1.z + f3.y * a1.w;
    }
    return acc;
}

// lane-partial dot: 1024 fp32 weights (GLOBAL, L2 via __ldcg) x 1024 fp32 acts (smem)
__device__ __forceinline__ float dotg(const float* __restrict__ wg,
                                      const float* __restrict__ a, int lane) {
    float acc = 0.f;
    int o = lane << 3;
#pragma unroll
    for (int it = 0; it < 4; ++it, o += 256) {
        float4 w0 = __ldcg(reinterpret_cast<const float4*>(wg + o));
        float4 w1 = __ldcg(reinterpret_cast<const float4*>(wg + o + 4));
        float4 a0 = *reinterpret_cast<const float4*>(a + o);
        float4 a1 = *reinterpret_cast<const float4*>(a + o + 4);
        acc += w0.x * a0.x + w0.y * a0.y + w0.z * a0.z + w0.w * a0.w
             + w1.x * a1.x + w1.y * a1.y + w1.z * a1.z + w1.w * a1.w;
    }
    return acc;
}

#define BAR_ARRIVE()                                           \
    do {                                                       \
        ++nbar;                                                \
        if (tid == 0) { __threadfence(); atomicAdd(&g_cnt2, 1u); } \
    } while (0)

#define BAR_WAIT()                                             \
    do {                                                       \
        if (tid == 0) {                                        \
            unsigned tgt = base + nbar * NBLK;                 \
            while ((int)(*(volatile unsigned*)&g_cnt2 - tgt) < 0) { } \
            __threadfence();                                   \
        }                                                      \
        __syncthreads();                                       \
    } while (0)

// ---------------- smem layout (bytes) — weights RESIDENT for the whole kernel ----
#define OFF_W1TD 0         // Wih1 TD half, 21 rows x 2048B fp16
#define OFF_W2TD 43008     // Wih2 TD half, 21 rows
#define OFF_W2S  86016     // Wih2 BU half, 21 rows
#define OFF_W3   129024    // Wih3, 21 rows
#define OFF_PW1  172032    // W1, 7 rows
#define OFF_PW2  186368    // W2, 7 rows
#define OFF_PM1  200704    // M1 = Wih1_bu @ W0, 21 rows x 64 fp32
#define OFF_ACTA 206080
#define OFF_ACTB 210176
#define OFF_ACTC 214272
#define OFF_ACTD 218368
#define OFF_N0   222464
#define OFF_GBUF 222720
#define OFF_ZP2  222848
#define OFF_CB1  222976
#define SMEM_BYTES 223104
// phase-0 W0 fp16 scratch (114,688 B at offset 0) overlaps the weight region; it
// is consumed (-> M1 at OFF_PM1, outside scratch) BEFORE the weights are filled.

__global__ void __launch_bounds__(NT, 1) predcells_kernel(
    const float* __restrict__ x,
    const float* __restrict__ W0w, const float* __restrict__ W0b,
    const float* __restrict__ W1w, const float* __restrict__ W1b,
    const float* __restrict__ W2w, const float* __restrict__ W2b,
    const float* __restrict__ Wih1, const float* __restrict__ b1,
    const float* __restrict__ Wih2, const float* __restrict__ b2,
    const float* __restrict__ Wih3, const float* __restrict__ b3,
    const float* __restrict__ V1w, const float* __restrict__ V1b,
    const float* __restrict__ V2w, const float* __restrict__ V2b,
    const float* __restrict__ V3w, const float* __restrict__ V3b,
    const int* __restrict__ iternum, float* __restrict__ out) {
    extern __shared__ char smem[];
    __half* pW1TD = (__half*)(smem + OFF_W1TD);
    __half* pW2TD = (__half*)(smem + OFF_W2TD);
    __half* pW2S  = (__half*)(smem + OFF_W2S);
    __half* pW3   = (__half*)(smem + OFF_W3);
    __half* pW1h  = (__half*)(smem + OFF_PW1);
    __half* pW2h  = (__half*)(smem + OFF_PW2);
    float*  pM1f  = (float*)(smem + OFF_PM1);
    float*  actA = (float*)(smem + OFF_ACTA);
    float*  actB = (float*)(smem + OFF_ACTB);
    float*  actC = (float*)(smem + OFF_ACTC);
    float*  actD = (float*)(smem + OFF_ACTD);
    float*  n0   = (float*)(smem + OFF_N0);
    float*  gbuf = (float*)(smem + OFF_GBUF);
    float*  zp2s = (float*)(smem + OFF_ZP2);
    float*  cb1s = (float*)(smem + OFF_CB1);

    const int tid = threadIdx.x;
    const int cta = blockIdx.x;
    const int w = tid >> 5;
    const int lane = tid & 31;
    const int nj = (cta < H - 6 * NBLK) ? 7 : 6;

    const int jlw = w / 3, gatew = w % 3;
    const int j1 = cta + jlw * NBLK;
    const bool lstmw = (w < 21) && (jlw < nj);
    const int gofs = (gatew == 0) ? 0 : (gatew == 1) ? 2 * H : 3 * H;
    const int jl = w - 21;
    const int j7 = cta + jl * NBLK;
    const bool sevw = (w >= 21 && w < 28) && (jl < nj);
    const bool v1w = (w == 28) && (cta < C);
    const bool lossw = (cta == 0) && (w == 31);

    const unsigned base = *(volatile unsigned*)&g_base;
    unsigned nbar = 0;

    // =================== phase 0: per-CTA convert + fuse (all local) ===================
    {
        // 1) W0 -> smem fp16 scratch (overlaps weight region; consumed before fill)
        __half* W0s = (__half*)smem;
        for (int i = tid; i < H * C; i += NT) W0s[i] = __float2half(W0w[i]);
        if (cta == 0) {
            for (int i = tid; i < H; i += NT) {
                g_TD1[i] = 0.f; g_TD2[i] = 0.f;
                g_r2[i] = 0.f; g_r3[i] = 0.f;
                g_s2[i] = 0.f; g_s3[i] = 0.f; g_BU2[i] = 0.f;
            }
            if (tid < 64) g_r1[tid] = 0.f;
        }
        __syncthreads();

        // 2) M1 = Wih1_bu @ W0 (fp32), cb1 = b1 + Wih1_bu @ W0b  (per-CTA rows only)
        if (lstmw) {
            const float* wrow = Wih1 + (size_t)(gofs + j1) * (2 * H);
            float acc0 = 0.f, acc1 = 0.f, accb = 0.f;
            for (int k0 = 0; k0 < H; k0 += 32) {
                float wv = wrow[k0 + lane];
                accb += wv * W0b[k0 + lane];
#pragma unroll 8
                for (int kk = 0; kk < 32; ++kk) {
                    float ww = __shfl_sync(0xffffffffu, wv, kk);
                    int k = k0 + kk;
                    acc0 += ww * __half2float(W0s[k * C + lane]);
                    float w1v = (lane < C - 32) ? __half2float(W0s[k * C + lane + 32]) : 0.f;
                    acc1 += ww * w1v;
                }
            }
            pM1f[w * 64 + lane] = acc0;
            if (lane < C - 32) pM1f[w * 64 + lane + 32] = acc1;
            float cb = wred(accb);
            if (lane == 0) cb1s[w] = b1[gofs + j1] + cb;
        }
        __syncthreads();

        // 3) fill resident fp16 weights — each CTA its own rows, straight from fp32 input
        if (lstmw) {
            const float4* s1a = (const float4*)(Wih1 + (size_t)(gofs + j1) * (2 * H) + H);
            const float4* s2t = (const float4*)(Wih2 + (size_t)(gofs + j1) * (2 * H) + H);
            const float4* s2s = (const float4*)(Wih2 + (size_t)(gofs + j1) * (2 * H));
            const float4* s3a = (const float4*)(Wih3 + (size_t)(gofs + j1) * H);
            __half2* d1 = (__half2*)(pW1TD + w * 1024);
            __half2* d2 = (__half2*)(pW2TD + w * 1024);
            __half2* d3 = (__half2*)(pW2S  + w * 1024);
            __half2* d4 = (__half2*)(pW3   + w * 1024);
            for (int i = lane; i < 256; i += 32) {
                float4 v;
                v = __ldcg(s1a + i); d1[i*2] = __floats2half2_rn(v.x, v.y); d1[i*2+1] = __floats2half2_rn(v.z, v.w);
                v = __ldcg(s2t + i); d2[i*2] = __floats2half2_rn(v.x, v.y); d2[i*2+1] = __floats2half2_rn(v.z, v.w);
                v = __ldcg(s2s + i); d3[i*2] = __floats2half2_rn(v.x, v.y); d3[i*2+1] = __floats2half2_rn(v.z, v.w);
                v = __ldcg(s3a + i); d4[i*2] = __floats2half2_rn(v.x, v.y); d4[i*2+1] = __floats2half2_rn(v.z, v.w);
            }
        } else if (sevw) {
            const float4* sw1 = (const float4*)(W1w + (size_t)j7 * H);
            const float4* sw2 = (const float4*)(W2w + (size_t)j7 * H);
            __half2* d1 = (__half2*)(pW1h + jl * 1024);
            __half2* d2 = (__half2*)(pW2h + jl * 1024);
            for (int i = lane; i < 256; i += 32) {
                float4 v;
                v = __ldcg(sw1 + i); d1[i*2] = __floats2half2_rn(v.x, v.y); d1[i*2+1] = __floats2half2_rn(v.z, v.w);
                v = __ldcg(sw2 + i); d2[i*2] = __floats2half2_rn(v.x, v.y); d2[i*2+1] = __floats2half2_rn(v.z, v.w);
            }
        }
        __syncthreads();
    }
    // one grid barrier: cta0's zero-init must be visible to all
    BAR_ARRIVE();
    BAR_WAIT();

    // hoisted loop-invariant scalars
    float r_cb1 = 0.f, r_b2 = 0.f, r_b3 = 0.f;
    float r_w1b = 0.f, r_w2b = 0.f, r_v2b = 0.f, r_v3b = 0.f, r_v1b = 0.f;
    if (lstmw) {
        r_cb1 = cb1s[w];
        r_b2  = b2[gofs + j1];
        r_b3  = b3[gofs + j1];
    }
    if (sevw) { r_w1b = W1b[j7]; r_w2b = W2b[j7]; r_v2b = V2b[j7]; r_v3b = V3b[j7]; }
    if (v1w) r_v1b = V1b[cta];

    float L0 = 0.f, L1 = 0.f, L2 = 0.f;

    for (int k = 0; k < T; ++k) {
        // ===== SP0: P1(k) z1->s1 || P4(k-1): nTD2, BU2=W2@nTD2, r2=V2@s2, loss2 =====
        {
            float aTD1 = __ldcg(&g_TD1[tid]);
            float s2v  = __ldcg(&g_s2[tid]);
            float r3v  = __ldcg(&g_r3[tid]);
            float ntd2 = s2v - r3v;
            actA[tid] = aTD1; actB[tid] = ntd2; actC[tid] = s2v;
            if (tid < 64)
                n0[tid] = (tid < C) ? (x[k * C + tid] - __ldcg(&g_r1[tid])) : 0.f;
            if (cta == 0) __stcg(&g_TD2[tid], ntd2);
            __syncthreads();
            if (lstmw) {
                float p = dotp(pW1TD + (size_t)w * 1024, actA, lane);
                const float* m = pM1f + w * 64;
                p += m[lane] * n0[lane];
                if (lane < C - 32) p += m[lane + 32] * n0[lane + 32];
                float z1 = wred(p);
                if (lane == 0) gbuf[w] = z1 + r_cb1;
            } else if (sevw && k > 0) {
                float bu  = wred(dotp(pW2h + (size_t)jl * 1024, actB, lane));
                float r2n = wred(dotg(V2w + (size_t)j7 * 1024, actC, lane));
                if (lane == 0) {
                    __stcg(&g_BU2[j7], bu + r_w2b);
                    __stcg(&g_r2[j7], r2n + r_v2b);
                }
            } else if (lossw) {
                float v = fabsf(n0[lane]);
                if (lane < C - 32) v += fabsf(n0[lane + 32]);
                L0 += v;
                if (k > 0) {
                    float v2 = 0.f;
                    for (int m2 = lane; m2 < H; m2 += 32) v2 += fabsf(actB[m2]);
                    L2 += v2;
                }
            }
            __syncthreads();
            if (tid < nj) {
                float zi = gbuf[tid * 3], zg = gbuf[tid * 3 + 1], zo = gbuf[tid * 3 + 2];
                __stcg(&g_s1[cta + tid * NBLK], sigm(zo) * tanhf(sigm(zi) * tanhf(zg)));
            }
            __syncthreads();
            BAR_ARRIVE();
            BAR_WAIT();
        }
        // ===== SP1: P2(k): zp2, BU1, r1=V1@s1, loss1 || P5(k-1): z3->s3 =====
        {
            float aTD2 = __ldcg(&g_TD2[tid]);
            float bu2v = __ldcg(&g_BU2[tid]);
            float s1v  = __ldcg(&g_s1[tid]);
            float r2v  = __ldcg(&g_r2[tid]);
            float ntd1 = s1v - r2v;
            actA[tid] = aTD2; actB[tid] = bu2v; actC[tid] = ntd1; actD[tid] = s1v;
            if (cta == 0) __stcg(&g_TD1[tid], ntd1);
            __syncthreads();
            if (lstmw) {
                float zp = wred(dotp(pW2TD + (size_t)w * 1024, actA, lane));
                if (lane == 0) zp2s[w] = zp + r_b2;
                if (k > 0) {
                    float z3 = wred(dotp(pW3 + (size_t)w * 1024, actB, lane));
                    if (lane == 0) gbuf[w] = z3 + r_b3;
                }
            } else if (sevw) {
                float bu = wred(dotp(pW1h + (size_t)jl * 1024, actC, lane));
                if (lane == 0) __stcg(&g_BU1[j7], bu + r_w1b);
            } else if (v1w) {
                float r1n = wred(dotg(V1w + (size_t)cta * 1024, actD, lane));
                if (lane == 0) __stcg(&g_r1[cta], r1n + r_v1b);
            } else if (lossw) {
                float v = 0.f;
                for (int m2 = lane; m2 < H; m2 += 32) v += fabsf(actC[m2]);
                L1 += v;
            }
            __syncthreads();
            if (k > 0 && tid < nj) {
                float zi = gbuf[tid * 3], zg = gbuf[tid * 3 + 1], zo = gbuf[tid * 3 + 2];
                __stcg(&g_s3[cta + tid * NBLK], sigm(zo) * tanhf(sigm(zi) * tanhf(zg)));
            }
            __syncthreads();
            BAR_ARRIVE();
            BAR_WAIT();
        }
        // ===== SP2: P3(k): z2 = Wih2s@BU1 + zp2 -> s2 || r3 = V3@s3(k-1) =====
        {
            actA[tid] = __ldcg(&g_BU1[tid]);
            actB[tid] = __ldcg(&g_s3[tid]);
            __syncthreads();
            if (lstmw) {
                float z2 = wred(dotp(pW2S + (size_t)w * 1024, actA, lane));
                if (lane == 0) gbuf[w] = z2 + zp2s[w];
            } else if (sevw && k > 0) {
                float r3n = wred(dotg(V3w + (size_t)j7 * 1024, actB, lane));
                if (lane == 0) __stcg(&g_r3[j7], r3n + r_v3b);
            }
            __syncthreads();
            if (tid < nj) {
                float zi = gbuf[tid * 3], zg = gbuf[tid * 3 + 1], zo = gbuf[tid * 3 + 2];
                __stcg(&g_s2[cta + tid * NBLK], sigm(zo) * tanhf(sigm(zi) * tanhf(zg)));
            }
            __syncthreads();
            BAR_ARRIVE();
            BAR_WAIT();
        }
    }

    // pipeline drain: final loss2 term |nTD2(T-1)| = |s2(T-1) - V3@s3(T-2)|
    if (lossw) {
        float v = 0.f;
        for (int m2 = lane; m2 < H; m2 += 32)
            v += fabsf(__ldcg(&g_s2[m2]) - __ldcg(&g_r3[m2]));
        L2 += v;
        float l0 = wred(L0), l1 = wred(L1), l2 = wred(L2);
        if (lane == 0) {
            float lam = (iternum[0] <= 1000) ? 1e-4f : 1e-2f;
            out[0] = l0 + lam * l1 + lam * lam * l2;
        }
    }

    if (cta == 0 && tid == 0)
        *(volatile unsigned*)&g_base = base + (unsigned)NBAR_TOTAL * NBLK;
}

extern "C" void kernel_launch(void* const* d_in, const int* in_sizes, int n_in,
                              void* d_out, int out_size) {
    (void)in_sizes; (void)n_in; (void)out_size;
    const float* x    = (const float*)d_in[0];
    const float* W0w  = (const float*)d_in[1];
    const float* W0b  = (const float*)d_in[2];
    const float* W1w  = (const float*)d_in[3];
    const float* W1b  = (const float*)d_in[4];
    const float* W2w  = (const float*)d_in[5];
    const float* W2b  = (const float*)d_in[6];
    const float* Wih1 = (const float*)d_in[7];
    const float* b1   = (const float*)d_in[8];
    const float* Wih2 = (const float*)d_in[9];
    const float* b2   = (const float*)d_in[10];
    const float* Wih3 = (const float*)d_in[11];
    const float* b3   = (const float*)d_in[12];
    const float* V1w  = (const float*)d_in[13];
    const float* V1b  = (const float*)d_in[14];
    const float* V2w  = (const float*)d_in[15];
    const float* V2b  = (const float*)d_in[16];
    const float* V3w  = (const float*)d_in[17];
    const float* V3b  = (const float*)d_in[18];
    const int*   itn  = (const int*)d_in[19];

    static bool attr_set = false;
    if (!attr_set) {
        cudaFuncSetAttribute(predcells_kernel,
                             cudaFuncAttributeMaxDynamicSharedMemorySize, SMEM_BYTES);
        attr_set = true;
    }
    predcells_kernel<<<NBLK, NT, SMEM_BYTES>>>(
        x, W0w, W0b, W1w, W1b, W2w, W2b, Wih1, b1, Wih2, b2, Wih3, b3,
        V1w, V1b, V2w, V2b, V3w, V3b, itn, (float*)d_out);
}

// round 11
// speedup vs baseline: 3.9377x; 1.0532x over previous
#include <cuda_runtime.h>
#include <cuda_fp16.h>
#include <cstdint>

#define H 1024
#define C 56
#define T 64
#define NBLK 148
#define NT 1024

// ---------------- persistent global state (activations only; weights live in smem) ----
__device__ __align__(16) float g_s1[H], g_s2[H], g_s3[H], g_BU1[H], g_BU2[H];
__device__ __align__(16) float g_TD1[H], g_TD2[H];
__device__ __align__(16) float g_r1[64], g_r2[H], g_r3[H];

// ---------------- monotonic-counter grid barrier, GPU-scope ops ----------------
// R10 and all prior variants polled via CUDA `volatile` (-> LDG.E.STRONG.SYS,
// system scope). R11: arrival is a single red.release.gpu (orders the CTA's
// prior stores via the bar.sync happens-before chain; no separate MEMBAR, no
// ATOM return), and the poll is ld.acquire.gpu (L2-scope RTT, not SYS).
__device__ unsigned g_cnt2;    // zero at load; grows monotonically forever
__device__ unsigned g_base;    // counter value at the start of this launch

#define NBAR_TOTAL (1 + 3 * T)

__device__ __forceinline__ float sigm(float x) { return 1.0f / (1.0f + expf(-x)); }

__device__ __forceinline__ float wred(float v) {
#pragma unroll
    for (int o = 16; o; o >>= 1) v += __shfl_xor_sync(0xffffffffu, v, o);
    return v;
}

// lane-partial dot: 1024 fp16 weights (smem) x 1024 fp32 acts (smem)
__device__ __forceinline__ float dotp(const __half* __restrict__ ws,
                                      const float* __restrict__ a, int lane) {
    float acc = 0.f;
    int o = lane << 3;
#pragma unroll
    for (int it = 0; it < 4; ++it, o += 256) {
        uint4 u = *reinterpret_cast<const uint4*>(ws + o);
        float4 a0 = *reinterpret_cast<const float4*>(a + o);
        float4 a1 = *reinterpret_cast<const float4*>(a + o + 4);
        float2 f0 = __half22float2(*reinterpret_cast<__half2*>(&u.x));
        float2 f1 = __half22float2(*reinterpret_cast<__half2*>(&u.y));
        float2 f2 = __half22float2(*reinterpret_cast<__half2*>(&u.z));
        float2 f3 = __half22float2(*reinterpret_cast<__half2*>(&u.w));
        acc += f0.x * a0.x + f0.y * a0.y + f1.x * a0.z + f1.y * a0.w
             + f2.x * a1.x + f2.y * a1.y + f3.x * a1.z + f3.y * a1.w;
    }
    return acc;
}

// lane-partial dot: 1024 fp32 weights (GLOBAL, L2 via __ldcg) x 1024 fp32 acts (smem)
__device__ __forceinline__ float dotg(const float* __restrict__ wg,
                                      const float* __restrict__ a, int lane) {
    float acc = 0.f;
    int o = lane << 3;
#pragma unroll
    for (int it = 0; it < 4; ++it, o += 256) {
        float4 w0 = __ldcg(reinterpret_cast<const float4*>(wg + o));
        float4 w1 = __ldcg(reinterpret_cast<const float4*>(wg + o + 4));
        float4 a0 = *reinterpret_cast<const float4*>(a + o);
        float4 a1 = *reinterpret_cast<const float4*>(a + o + 4);
        acc += w0.x * a0.x + w0.y * a0.y + w0.z * a0.z + w0.w * a0.w
             + w1.x * a1.x + w1.y * a1.y + w1.z * a1.z + w1.w * a1.w;
    }
    return acc;
}

#define BAR_ARRIVE()                                                        \
    do {                                                                    \
        ++nbar;                                                             \
        if (tid == 0)                                                       \
            asm volatile("red.release.gpu.global.add.u32 [%0], %1;"         \
                         :: "l"(&g_cnt2), "r"(1u) : "memory");              \
    } while (0)

#define BAR_WAIT()                                                          \
    do {                                                                    \
        if (tid == 0) {                                                     \
            unsigned tgt = base + nbar * NBLK;                              \
            unsigned v;                                                     \
            do {                                                            \
                asm volatile("ld.acquire.gpu.global.u32 %0, [%1];"          \
                             : "=r"(v) : "l"(&g_cnt2) : "memory");          \
            } while ((int)(v - tgt) < 0);                                   \
        }                                                                   \
        __syncthreads();                                                    \
    } while (0)

// ---------------- smem layout (bytes) — weights RESIDENT for the whole kernel ----
#define OFF_W1TD 0         // Wih1 TD half, 21 rows x 2048B fp16
#define OFF_W2TD 43008     // Wih2 TD half, 21 rows
#define OFF_W2S  86016     // Wih2 BU half, 21 rows
#define OFF_W3   129024    // Wih3, 21 rows
#define OFF_PW1  172032    // W1, 7 rows
#define OFF_PW2  186368    // W2, 7 rows
#define OFF_PM1  200704    // M1 = Wih1_bu @ W0, 21 rows x 64 fp32
#define OFF_ACTA 206080
#define OFF_ACTB 210176
#define OFF_ACTC 214272
#define OFF_ACTD 218368
#define OFF_N0   222464
#define OFF_GBUF 222720
#define OFF_ZP2  222848
#define OFF_CB1  222976
#define SMEM_BYTES 223104
// phase-0 W0 fp16 scratch (114,688 B at offset 0) overlaps the weight region; it
// is consumed (-> M1 at OFF_PM1, outside scratch) BEFORE the weights are filled.

__global__ void __launch_bounds__(NT, 1) predcells_kernel(
    const float* __restrict__ x,
    const float* __restrict__ W0w, const float* __restrict__ W0b,
    const float* __restrict__ W1w, const float* __restrict__ W1b,
    const float* __restrict__ W2w, const float* __restrict__ W2b,
    const float* __restrict__ Wih1, const float* __restrict__ b1,
    const float* __restrict__ Wih2, const float* __restrict__ b2,
    const float* __restrict__ Wih3, const float* __restrict__ b3,
    const float* __restrict__ V1w, const float* __restrict__ V1b,
    const float* __restrict__ V2w, const float* __restrict__ V2b,
    const float* __restrict__ V3w, const float* __restrict__ V3b,
    const int* __restrict__ iternum, float* __restrict__ out) {
    extern __shared__ char smem[];
    __half* pW1TD = (__half*)(smem + OFF_W1TD);
    __half* pW2TD = (__half*)(smem + OFF_W2TD);
    __half* pW2S  = (__half*)(smem + OFF_W2S);
    __half* pW3   = (__half*)(smem + OFF_W3);
    __half* pW1h  = (__half*)(smem + OFF_PW1);
    __half* pW2h  = (__half*)(smem + OFF_PW2);
    float*  pM1f  = (float*)(smem + OFF_PM1);
    float*  actA = (float*)(smem + OFF_ACTA);
    float*  actB = (float*)(smem + OFF_ACTB);
    float*  actC = (float*)(smem + OFF_ACTC);
    float*  actD = (float*)(smem + OFF_ACTD);
    float*  n0   = (float*)(smem + OFF_N0);
    float*  gbuf = (float*)(smem + OFF_GBUF);
    float*  zp2s = (float*)(smem + OFF_ZP2);
    float*  cb1s = (float*)(smem + OFF_CB1);

    const int tid = threadIdx.x;
    const int cta = blockIdx.x;
    const int w = tid >> 5;
    const int lane = tid & 31;
    const int nj = (cta < H - 6 * NBLK) ? 7 : 6;

    const int jlw = w / 3, gatew = w % 3;
    const int j1 = cta + jlw * NBLK;
    const bool lstmw = (w < 21) && (jlw < nj);
    const int gofs = (gatew == 0) ? 0 : (gatew == 1) ? 2 * H : 3 * H;
    const int jl = w - 21;
    const int j7 = cta + jl * NBLK;
    const bool sevw = (w >= 21 && w < 28) && (jl < nj);
    const bool v1w = (w == 28) && (cta < C);
    const bool lossw = (cta == 0) && (w == 31);

    unsigned base;
    asm volatile("ld.acquire.gpu.global.u32 %0, [%1];" : "=r"(base) : "l"(&g_base) : "memory");
    unsigned nbar = 0;

    // =================== phase 0: per-CTA convert + fuse (all local) ===================
    {
        __half* W0s = (__half*)smem;
        for (int i = tid; i < H * C; i += NT) W0s[i] = __float2half(W0w[i]);
        if (cta == 0) {
            for (int i = tid; i < H; i += NT) {
                g_TD1[i] = 0.f; g_TD2[i] = 0.f;
                g_r2[i] = 0.f; g_r3[i] = 0.f;
                g_s2[i] = 0.f; g_s3[i] = 0.f; g_BU2[i] = 0.f;
            }
            if (tid < 64) g_r1[tid] = 0.f;
        }
        __syncthreads();

        if (lstmw) {
            const float* wrow = Wih1 + (size_t)(gofs + j1) * (2 * H);
            float acc0 = 0.f, acc1 = 0.f, accb = 0.f;
            for (int k0 = 0; k0 < H; k0 += 32) {
                float wv = wrow[k0 + lane];
                accb += wv * W0b[k0 + lane];
#pragma unroll 8
                for (int kk = 0; kk < 32; ++kk) {
                    float ww = __shfl_sync(0xffffffffu, wv, kk);
                    int k = k0 + kk;
                    acc0 += ww * __half2float(W0s[k * C + lane]);
                    float w1v = (lane < C - 32) ? __half2float(W0s[k * C + lane + 32]) : 0.f;
                    acc1 += ww * w1v;
                }
            }
            pM1f[w * 64 + lane] = acc0;
            if (lane < C - 32) pM1f[w * 64 + lane + 32] = acc1;
            float cb = wred(accb);
            if (lane == 0) cb1s[w] = b1[gofs + j1] + cb;
        }
        __syncthreads();

        if (lstmw) {
            const float4* s1a = (const float4*)(Wih1 + (size_t)(gofs + j1) * (2 * H) + H);
            const float4* s2t = (const float4*)(Wih2 + (size_t)(gofs + j1) * (2 * H) + H);
            const float4* s2s = (const float4*)(Wih2 + (size_t)(gofs + j1) * (2 * H));
            const float4* s3a = (const float4*)(Wih3 + (size_t)(gofs + j1) * H);
            __half2* d1 = (__half2*)(pW1TD + w * 1024);
            __half2* d2 = (__half2*)(pW2TD + w * 1024);
            __half2* d3 = (__half2*)(pW2S  + w * 1024);
            __half2* d4 = (__half2*)(pW3   + w * 1024);
            for (int i = lane; i < 256; i += 32) {
                float4 v;
                v = __ldcg(s1a + i); d1[i*2] = __floats2half2_rn(v.x, v.y); d1[i*2+1] = __floats2half2_rn(v.z, v.w);
                v = __ldcg(s2t + i); d2[i*2] = __floats2half2_rn(v.x, v.y); d2[i*2+1] = __floats2half2_rn(v.z, v.w);
                v = __ldcg(s2s + i); d3[i*2] = __floats2half2_rn(v.x, v.y); d3[i*2+1] = __floats2half2_rn(v.z, v.w);
                v = __ldcg(s3a + i); d4[i*2] = __floats2half2_rn(v.x, v.y); d4[i*2+1] = __floats2half2_rn(v.z, v.w);
            }
        } else if (sevw) {
            const float4* sw1 = (const float4*)(W1w + (size_t)j7 * H);
            const float4* sw2 = (const float4*)(W2w + (size_t)j7 * H);
            __half2* d1 = (__half2*)(pW1h + jl * 1024);
            __half2* d2 = (__half2*)(pW2h + jl * 1024);
            for (int i = lane; i < 256; i += 32) {
                float4 v;
                v = __ldcg(sw1 + i); d1[i*2] = __floats2half2_rn(v.x, v.y); d1[i*2+1] = __floats2half2_rn(v.z, v.w);
                v = __ldcg(sw2 + i); d2[i*2] = __floats2half2_rn(v.x, v.y); d2[i*2+1] = __floats2half2_rn(v.z, v.w);
            }
        }
        __syncthreads();
    }
    BAR_ARRIVE();
    BAR_WAIT();

    float r_cb1 = 0.f, r_b2 = 0.f, r_b3 = 0.f;
    float r_w1b = 0.f, r_w2b = 0.f, r_v2b = 0.f, r_v3b = 0.f, r_v1b = 0.f;
    if (lstmw) {
        r_cb1 = cb1s[w];
        r_b2  = b2[gofs + j1];
        r_b3  = b3[gofs + j1];
    }
    if (sevw) { r_w1b = W1b[j7]; r_w2b = W2b[j7]; r_v2b = V2b[j7]; r_v3b = V3b[j7]; }
    if (v1w) r_v1b = V1b[cta];

    float L0 = 0.f, L1 = 0.f, L2 = 0.f;

    for (int k = 0; k < T; ++k) {
        // ===== SP0: P1(k) z1->s1 || P4(k-1): nTD2, BU2=W2@nTD2, r2=V2@s2, loss2 =====
        {
            float aTD1 = __ldcg(&g_TD1[tid]);
            float s2v  = __ldcg(&g_s2[tid]);
            float r3v  = __ldcg(&g_r3[tid]);
            float ntd2 = s2v - r3v;
            actA[tid] = aTD1; actB[tid] = ntd2; actC[tid] = s2v;
            if (tid < 64)
                n0[tid] = (tid < C) ? (x[k * C + tid] - __ldcg(&g_r1[tid])) : 0.f;
            if (cta == 0) __stcg(&g_TD2[tid], ntd2);
            __syncthreads();
            if (lstmw) {
                float p = dotp(pW1TD + (size_t)w * 1024, actA, lane);
                const float* m = pM1f + w * 64;
                p += m[lane] * n0[lane];
                if (lane < C - 32) p += m[lane + 32] * n0[lane + 32];
                float z1 = wred(p);
                if (lane == 0) gbuf[w] = z1 + r_cb1;
            } else if (sevw && k > 0) {
                float bu  = wred(dotp(pW2h + (size_t)jl * 1024, actB, lane));
                float r2n = wred(dotg(V2w + (size_t)j7 * 1024, actC, lane));
                if (lane == 0) {
                    __stcg(&g_BU2[j7], bu + r_w2b);
                    __stcg(&g_r2[j7], r2n + r_v2b);
                }
            } else if (lossw) {
                float v = fabsf(n0[lane]);
                if (lane < C - 32) v += fabsf(n0[lane + 32]);
                L0 += v;
                if (k > 0) {
                    float v2 = 0.f;
                    for (int m2 = lane; m2 < H; m2 += 32) v2 += fabsf(actB[m2]);
                    L2 += v2;
                }
            }
            __syncthreads();
            if (tid < nj) {
                float zi = gbuf[tid * 3], zg = gbuf[tid * 3 + 1], zo = gbuf[tid * 3 + 2];
                __stcg(&g_s1[cta + tid * NBLK], sigm(zo) * tanhf(sigm(zi) * tanhf(zg)));
            }
            __syncthreads();
            BAR_ARRIVE();
            BAR_WAIT();
        }
        // ===== SP1: P2(k): zp2, BU1, r1=V1@s1, loss1 || P5(k-1): z3->s3 =====
        {
            float aTD2 = __ldcg(&g_TD2[tid]);
            float bu2v = __ldcg(&g_BU2[tid]);
            float s1v  = __ldcg(&g_s1[tid]);
            float r2v  = __ldcg(&g_r2[tid]);
            float ntd1 = s1v - r2v;
            actA[tid] = aTD2; actB[tid] = bu2v; actC[tid] = ntd1; actD[tid] = s1v;
            if (cta == 0) __stcg(&g_TD1[tid], ntd1);
            __syncthreads();
            if (lstmw) {
                float zp = wred(dotp(pW2TD + (size_t)w * 1024, actA, lane));
                if (lane == 0) zp2s[w] = zp + r_b2;
                if (k > 0) {
                    float z3 = wred(dotp(pW3 + (size_t)w * 1024, actB, lane));
                    if (lane == 0) gbuf[w] = z3 + r_b3;
                }
            } else if (sevw) {
                float bu = wred(dotp(pW1h + (size_t)jl * 1024, actC, lane));
                if (lane == 0) __stcg(&g_BU1[j7], bu + r_w1b);
            } else if (v1w) {
                float r1n = wred(dotg(V1w + (size_t)cta * 1024, actD, lane));
                if (lane == 0) __stcg(&g_r1[cta], r1n + r_v1b);
            } else if (lossw) {
                float v = 0.f;
                for (int m2 = lane; m2 < H; m2 += 32) v += fabsf(actC[m2]);
                L1 += v;
            }
            __syncthreads();
            if (k > 0 && tid < nj) {
                float zi = gbuf[tid * 3], zg = gbuf[tid * 3 + 1], zo = gbuf[tid * 3 + 2];
                __stcg(&g_s3[cta + tid * NBLK], sigm(zo) * tanhf(sigm(zi) * tanhf(zg)));
            }
            __syncthreads();
            BAR_ARRIVE();
            BAR_WAIT();
        }
        // ===== SP2: P3(k): z2 = Wih2s@BU1 + zp2 -> s2 || r3 = V3@s3(k-1) =====
        {
            actA[tid] = __ldcg(&g_BU1[tid]);
            actB[tid] = __ldcg(&g_s3[tid]);
            __syncthreads();
            if (lstmw) {
                float z2 = wred(dotp(pW2S + (size_t)w * 1024, actA, lane));
                if (lane == 0) gbuf[w] = z2 + zp2s[w];
            } else if (sevw && k > 0) {
                float r3n = wred(dotg(V3w + (size_t)j7 * 1024, actB, lane));
                if (lane == 0) __stcg(&g_r3[j7], r3n + r_v3b);
            }
            __syncthreads();
            if (tid < nj) {
                float zi = gbuf[tid * 3], zg = gbuf[tid * 3 + 1], zo = gbuf[tid * 3 + 2];
                __stcg(&g_s2[cta + tid * NBLK], sigm(zo) * tanhf(sigm(zi) * tanhf(zg)));
            }
            __syncthreads();
            BAR_ARRIVE();
            BAR_WAIT();
        }
    }

    // pipeline drain: final loss2 term |nTD2(T-1)| = |s2(T-1) - V3@s3(T-2)|
    if (lossw) {
        float v = 0.f;
        for (int m2 = lane; m2 < H; m2 += 32)
            v += fabsf(__ldcg(&g_s2[m2]) - __ldcg(&g_r3[m2]));
        L2 += v;
        float l0 = wred(L0), l1 = wred(L1), l2 = wred(L2);
        if (lane == 0) {
            float lam = (iternum[0] <= 1000) ? 1e-4f : 1e-2f;
            out[0] = l0 + lam * l1 + lam * lam * l2;
        }
    }

    if (cta == 0 && tid == 0) {
        unsigned nb = base + (unsigned)NBAR_TOTAL * NBLK;
        asm volatile("st.release.gpu.global.u32 [%0], %1;" :: "l"(&g_base), "r"(nb) : "memory");
    }
}

extern "C" void kernel_launch(void* const* d_in, const int* in_sizes, int n_in,
                              void* d_out, int out_size) {
    (void)in_sizes; (void)n_in; (void)out_size;
    const float* x    = (const float*)d_in[0];
    const float* W0w  = (const float*)d_in[1];
    const float* W0b  = (const float*)d_in[2];
    const float* W1w  = (const float*)d_in[3];
    const float* W1b  = (const float*)d_in[4];
    const float* W2w  = (const float*)d_in[5];
    const float* W2b  = (const float*)d_in[6];
    const float* Wih1 = (const float*)d_in[7];
    const float* b1   = (const float*)d_in[8];
    const float* Wih2 = (const float*)d_in[9];
    const float* b2   = (const float*)d_in[10];
    const float* Wih3 = (const float*)d_in[11];
    const float* b3   = (const float*)d_in[12];
    const float* V1w  = (const float*)d_in[13];
    const float* V1b  = (const float*)d_in[14];
    const float* V2w  = (const float*)d_in[15];
    const float* V2b  = (const float*)d_in[16];
    const float* V3w  = (const float*)d_in[17];
    const float* V3b  = (const float*)d_in[18];
    const int*   itn  = (const int*)d_in[19];

    static bool attr_set = false;
    if (!attr_set) {
        cudaFuncSetAttribute(predcells_kernel,
                             cudaFuncAttributeMaxDynamicSharedMemorySize, SMEM_BYTES);
        attr_set = true;
    }
    predcells_kernel<<<NBLK, NT, SMEM_BYTES>>>(
        x, W0w, W0b, W1w, W1b, W2w, W2b, Wih1, b1, Wih2, b2, Wih3, b3,
        V1w, V1b, V2w, V2b, V3w, V3b, itn, (float*)d_out);
}